// round 4
// baseline (speedup 1.0000x reference)
#include <cuda_runtime.h>
#include <math.h>

// ---------------- problem constants (fixed by setup_inputs) ----------------
#define Nn      16384       // nodes = B*L
#define Ee      131072      // edges (without self loops)
#define ETOT    (Ee + Nn)   // with self loops
#define Bsz     256         // batch
#define Lseq    64
#define Hd      256
#define NHEADS  8
#define F1      2048        // HEADS*H
#define G4      1024        // 4*H
#define NNODE_  37000

// ---------------- device scratch (static, allocation-free) ----------------
__device__ float g_x0  [(size_t)Nn * Hd];
__device__ float g_h1  [(size_t)Nn * F1];
__device__ float g_x1  [(size_t)Nn * F1];
__device__ float g_h2  [(size_t)Nn * Hd];
__device__ float g_out2[(size_t)Nn * Hd];
__device__ float g_xg  [(size_t)Nn * G4];
__device__ float g_as1 [Nn * NHEADS];
__device__ float g_ad1 [Nn * NHEADS];
__device__ float g_as2 [Nn];
__device__ float g_ad2 [Nn];
__device__ int   g_counts[Nn];
__device__ int   g_rowptr[Nn + 1];
__device__ int   g_cursor[Nn];
__device__ int   g_colsrc[ETOT];
__device__ int   g_len   [Bsz];
__device__ int   g_starts[Bsz];
__device__ int   g_nodeidx[Bsz * Lseq];
__device__ float g_gbuf[Bsz * G4];
__device__ float g_h   [Bsz * Hd];
__device__ float g_c   [Bsz * Hd];
__device__ float g_bsum[G4];

// ---------------- generic tiled SGEMM ----------------
// C[M,N] = A[M,K] @ op(B) (+ bias[n])
// BT=false: B is row-major [K,N].  BT=true: B is row-major [N,K] (C = A @ B^T).
// Requirements used here: M % BM == 0, K % BK == 0, K % 4 == 0, N % 4 == 0.
// N-edge guarded (needed for N = 37000).
template<int BM, int BN, int BK, int TM, int TN, bool BT>
__global__ void __launch_bounds__((BM / TM) * (BN / TN))
k_sgemm(const float* __restrict__ A, const float* __restrict__ B,
        float* __restrict__ C, int M, int N, int K,
        const float* __restrict__ bias)
{
    constexpr int THREADS = (BM / TM) * (BN / TN);
    constexpr int TX = BN / TN;

    __shared__ float As[BK][BM + 4];
    __shared__ float Bs[BK][BN + 4];

    const int tid = threadIdx.x;
    const int bm  = blockIdx.y * BM;
    const int bn  = blockIdx.x * BN;
    const int tx  = tid % TX;
    const int ty  = tid / TX;

    float acc[TM][TN];
#pragma unroll
    for (int i = 0; i < TM; i++)
#pragma unroll
        for (int j = 0; j < TN; j++) acc[i][j] = 0.f;

    constexpr int A4  = BM * BK / 4;
    constexpr int B4t = BN * BK / 4;   // BT tile: BN rows x BK cols
    constexpr int B4n = BK * BN / 4;   // NN tile: BK rows x BN cols

    for (int k0 = 0; k0 < K; k0 += BK) {
        // --- A tile: BM x BK, stored transposed As[k][m] ---
#pragma unroll
        for (int i4 = tid; i4 < A4; i4 += THREADS) {
            int off = i4 * 4;
            int r = off / BK, cc = off % BK;
            float4 v = *reinterpret_cast<const float4*>(
                &A[(size_t)(bm + r) * K + k0 + cc]);
            As[cc + 0][r] = v.x; As[cc + 1][r] = v.y;
            As[cc + 2][r] = v.z; As[cc + 3][r] = v.w;
        }
        // --- B tile ---
        if (BT) {
#pragma unroll
            for (int i4 = tid; i4 < B4t; i4 += THREADS) {
                int off = i4 * 4;
                int r = off / BK, cc = off % BK;
                float4 v;
                if (bn + r < N)
                    v = *reinterpret_cast<const float4*>(
                        &B[(size_t)(bn + r) * K + k0 + cc]);
                else
                    v = make_float4(0.f, 0.f, 0.f, 0.f);
                Bs[cc + 0][r] = v.x; Bs[cc + 1][r] = v.y;
                Bs[cc + 2][r] = v.z; Bs[cc + 3][r] = v.w;
            }
        } else {
#pragma unroll
            for (int i4 = tid; i4 < B4n; i4 += THREADS) {
                int off = i4 * 4;
                int r = off / BN, cc = off % BN;
                float4 v = *reinterpret_cast<const float4*>(
                    &B[(size_t)(k0 + r) * N + bn + cc]);
                *reinterpret_cast<float4*>(&Bs[r][cc]) = v;
            }
        }
        __syncthreads();

#pragma unroll
        for (int kk = 0; kk < BK; kk++) {
            float af[TM], bf[TN];
#pragma unroll
            for (int i = 0; i < TM; i++) af[i] = As[kk][ty * TM + i];
#pragma unroll
            for (int j = 0; j < TN; j++) bf[j] = Bs[kk][tx * TN + j];
#pragma unroll
            for (int i = 0; i < TM; i++)
#pragma unroll
                for (int j = 0; j < TN; j++) acc[i][j] += af[i] * bf[j];
        }
        __syncthreads();
    }

    // --- store with N guard + optional bias ---
#pragma unroll
    for (int i = 0; i < TM; i++) {
        int row = bm + ty * TM + i;
#pragma unroll
        for (int j = 0; j < TN; j += 4) {
            int col = bn + tx * TN + j;
            if (col + 3 < N) {
                float4 v;
                v.x = acc[i][j + 0] + (bias ? bias[col + 0] : 0.f);
                v.y = acc[i][j + 1] + (bias ? bias[col + 1] : 0.f);
                v.z = acc[i][j + 2] + (bias ? bias[col + 2] : 0.f);
                v.w = acc[i][j + 3] + (bias ? bias[col + 3] : 0.f);
                *reinterpret_cast<float4*>(&C[(size_t)row * N + col]) = v;
            } else {
#pragma unroll
                for (int u = 0; u < 4; u++) {
                    if (col + u < N)
                        C[(size_t)row * N + col + u] =
                            acc[i][j + u] + (bias ? bias[col + u] : 0.f);
                }
            }
        }
    }
}

// ---------------- embedding gather (emb[0] := 0) ----------------
__global__ void k_gather_x0(const int* __restrict__ ids,
                            const float* __restrict__ emb,
                            float* __restrict__ x0)
{
    int i = blockIdx.x, t = threadIdx.x;
    int id = ids[i];
    x0[(size_t)i * Hd + t] = (id == 0) ? 0.f : emb[(size_t)id * Hd + t];
}

// ---------------- attention logits ----------------
__global__ void k_alpha1(const float* __restrict__ h1,
                         const float* __restrict__ attS,
                         const float* __restrict__ attD,
                         float* __restrict__ outS, float* __restrict__ outD)
{
    int i = blockIdx.x;
    int w = threadIdx.x >> 5, lane = threadIdx.x & 31;
    const float* hp = h1 + (size_t)i * F1 + w * Hd;
    const float* ap = attS + w * Hd;
    const float* dp = attD + w * Hd;
    float ss = 0.f, sd = 0.f;
#pragma unroll
    for (int u = 0; u < 8; u++) {
        float v = hp[lane + 32 * u];
        ss += v * ap[lane + 32 * u];
        sd += v * dp[lane + 32 * u];
    }
#pragma unroll
    for (int o = 16; o; o >>= 1) {
        ss += __shfl_xor_sync(0xffffffffu, ss, o);
        sd += __shfl_xor_sync(0xffffffffu, sd, o);
    }
    if (lane == 0) { outS[i * NHEADS + w] = ss; outD[i * NHEADS + w] = sd; }
}

__global__ void k_alpha2(const float* __restrict__ h2,
                         const float* __restrict__ attS,
                         const float* __restrict__ attD,
                         float* __restrict__ outS, float* __restrict__ outD)
{
    __shared__ float shS[8], shD[8];
    int i = blockIdx.x, t = threadIdx.x;
    float v = h2[(size_t)i * Hd + t];
    float ss = v * attS[t], sd = v * attD[t];
    int lane = t & 31, w = t >> 5;
#pragma unroll
    for (int o = 16; o; o >>= 1) {
        ss += __shfl_xor_sync(0xffffffffu, ss, o);
        sd += __shfl_xor_sync(0xffffffffu, sd, o);
    }
    if (lane == 0) { shS[w] = ss; shD[w] = sd; }
    __syncthreads();
    if (t == 0) {
        float a = 0.f, b = 0.f;
#pragma unroll
        for (int u = 0; u < 8; u++) { a += shS[u]; b += shD[u]; }
        outS[i] = a; outD[i] = b;
    }
}

// ---------------- CSR build (group edges by dst) ----------------
__global__ void k_init_counts(int* __restrict__ counts)
{
    int i = blockIdx.x * blockDim.x + threadIdx.x;
    if (i < Nn) counts[i] = 1;   // self loop
}
__global__ void k_count_edges(const int* __restrict__ ei, int* __restrict__ counts)
{
    int e = blockIdx.x * blockDim.x + threadIdx.x;
    if (e < Ee) atomicAdd(&counts[ei[Ee + e]], 1);
}
__global__ void k_scan16k(const int* __restrict__ counts, int* __restrict__ rowptr)
{
    __shared__ int wsum[32];
    const int tid = threadIdx.x;           // 1024 threads
    const int per = Nn / 1024;             // 16
    const int base = tid * per;
    int c[16];
    int tot = 0;
#pragma unroll
    for (int u = 0; u < per; u++) { c[u] = counts[base + u]; tot += c[u]; }
    int lane = tid & 31, wid = tid >> 5;
    int v = tot;
#pragma unroll
    for (int o = 1; o < 32; o <<= 1) {
        int t2 = __shfl_up_sync(0xffffffffu, v, o);
        if (lane >= o) v += t2;
    }
    if (lane == 31) wsum[wid] = v;
    __syncthreads();
    if (wid == 0) {
        int w = wsum[lane];
#pragma unroll
        for (int o = 1; o < 32; o <<= 1) {
            int t2 = __shfl_up_sync(0xffffffffu, w, o);
            if (lane >= o) w += t2;
        }
        wsum[lane] = w;
    }
    __syncthreads();
    int run = (v - tot) + (wid > 0 ? wsum[wid - 1] : 0);
#pragma unroll
    for (int u = 0; u < per; u++) { rowptr[base + u] = run; run += c[u]; }
    if (tid == 1023) rowptr[Nn] = run;
}
__global__ void k_copy_cursor(const int* __restrict__ rowptr, int* __restrict__ cursor)
{
    int i = blockIdx.x * blockDim.x + threadIdx.x;
    if (i < Nn) cursor[i] = rowptr[i];
}
__global__ void k_scatter_edges(const int* __restrict__ ei,
                                int* __restrict__ cursor, int* __restrict__ colsrc)
{
    int e = blockIdx.x * blockDim.x + threadIdx.x;
    if (e < Ee) {
        int d = ei[Ee + e];
        int p = atomicAdd(&cursor[d], 1);
        colsrc[p] = ei[e];
    }
}
__global__ void k_scatter_loops(int* __restrict__ cursor, int* __restrict__ colsrc)
{
    int i = blockIdx.x * blockDim.x + threadIdx.x;
    if (i < Nn) {
        int p = atomicAdd(&cursor[i], 1);
        colsrc[p] = i;
    }
}

// ---------------- GAT aggregation (softmax over incoming edges) ----------------
__global__ void k_gat1_agg(const float* __restrict__ h1,
                           const float* __restrict__ aS, const float* __restrict__ aD,
                           const int* __restrict__ rowptr, const int* __restrict__ colsrc,
                           const float* __restrict__ b1, float* __restrict__ x1)
{
    int dst = blockIdx.x;
    int w = threadIdx.x >> 5, lane = threadIdx.x & 31;
    int beg = rowptr[dst], end = rowptr[dst + 1];
    float adv = aD[dst * NHEADS + w];

    float m = -3.4e38f;
    for (int e = beg; e < end; e++) {
        float v = aS[colsrc[e] * NHEADS + w] + adv;
        v = v > 0.f ? v : 0.2f * v;
        m = fmaxf(m, v);
    }
    float acc[8] = {0.f, 0.f, 0.f, 0.f, 0.f, 0.f, 0.f, 0.f};
    float sump = 0.f;
    for (int e = beg; e < end; e++) {
        int s = colsrc[e];
        float v = aS[s * NHEADS + w] + adv;
        v = v > 0.f ? v : 0.2f * v;
        float p = expf(v - m);
        sump += p;
        const float* hp = h1 + (size_t)s * F1 + w * Hd + lane;
#pragma unroll
        for (int u = 0; u < 8; u++) acc[u] += p * hp[u * 32];
    }
    float inv = 1.f / (sump + 1e-16f);
    float* xp = x1 + (size_t)dst * F1 + w * Hd + lane;
    const float* bp = b1 + w * Hd + lane;
#pragma unroll
    for (int u = 0; u < 8; u++) {
        float o = acc[u] * inv + bp[u * 32];
        xp[u * 32] = o > 0.f ? o : expm1f(o);   // ELU
    }
}

__global__ void k_gat2_agg(const float* __restrict__ h2,
                           const float* __restrict__ aS, const float* __restrict__ aD,
                           const int* __restrict__ rowptr, const int* __restrict__ colsrc,
                           const float* __restrict__ b2, float* __restrict__ out2)
{
    int dst = blockIdx.x, t = threadIdx.x;
    int beg = rowptr[dst], end = rowptr[dst + 1];
    float adv = aD[dst];
    float m = -3.4e38f;
    for (int e = beg; e < end; e++) {
        float v = aS[colsrc[e]] + adv;
        v = v > 0.f ? v : 0.2f * v;
        m = fmaxf(m, v);
    }
    float acc = 0.f, sump = 0.f;
    for (int e = beg; e < end; e++) {
        int s = colsrc[e];
        float v = aS[s] + adv;
        v = v > 0.f ? v : 0.2f * v;
        float p = expf(v - m);
        sump += p;
        acc += p * h2[(size_t)s * Hd + t];
    }
    out2[(size_t)dst * Hd + t] = acc / (sump + 1e-16f) + b2[t];
}

// ---------------- sequence bookkeeping ----------------
__global__ void k_zero_len(int* __restrict__ len) { len[threadIdx.x] = 0; }
__global__ void k_count_len(const int* __restrict__ batch, int* __restrict__ len)
{
    int i = blockIdx.x * blockDim.x + threadIdx.x;
    if (i < Nn) atomicAdd(&len[batch[i]], 1);
}
__global__ void k_scan256(const int* __restrict__ len, int* __restrict__ starts)
{
    __shared__ int wsum[8];
    int tid = threadIdx.x;
    int orig = len[tid];
    int v = orig;
    int lane = tid & 31, wid = tid >> 5;
#pragma unroll
    for (int o = 1; o < 32; o <<= 1) {
        int t2 = __shfl_up_sync(0xffffffffu, v, o);
        if (lane >= o) v += t2;
    }
    if (lane == 31) wsum[wid] = v;
    __syncthreads();
    if (tid == 0) {
        int s = 0;
#pragma unroll
        for (int u = 0; u < 8; u++) { int t2 = wsum[u]; wsum[u] = s; s += t2; }
    }
    __syncthreads();
    starts[tid] = (v - orig) + wsum[wid];
}
__global__ void k_nodeidx(const int* __restrict__ batch, const int* __restrict__ starts,
                          int* __restrict__ nodeidx)
{
    int i = blockIdx.x * blockDim.x + threadIdx.x;
    if (i < Nn) {
        int b = batch[i];
        int p = i - starts[b];
        if (p >= 0 && p < Lseq) nodeidx[b * Lseq + p] = i;
    }
}
__global__ void k_bsum(const float* __restrict__ bih, const float* __restrict__ bhh,
                       float* __restrict__ bs)
{
    int k = blockIdx.x * blockDim.x + threadIdx.x;
    if (k < G4) bs[k] = bih[k] + bhh[k];
}
__global__ void k_zero_hc(float* __restrict__ h, float* __restrict__ c)
{
    int i = blockIdx.x * blockDim.x + threadIdx.x;
    h[i] = 0.f; c[i] = 0.f;
}

// ---------------- LSTM gate step ----------------
__global__ void k_gate(const float* __restrict__ gbuf, const float* __restrict__ xg,
                       const int* __restrict__ nodeidx, const int* __restrict__ len,
                       float* __restrict__ h, float* __restrict__ c, int t)
{
    int b = blockIdx.x, j = threadIdx.x;
    if (t >= len[b]) return;
    int node = nodeidx[b * Lseq + t];
    const float* xp = xg + (size_t)node * G4;
    const float* gp = gbuf + (size_t)b * G4;
    float gi = gp[j]       + xp[j];
    float gf = gp[256 + j] + xp[256 + j];
    float gg = gp[512 + j] + xp[512 + j];
    float go = gp[768 + j] + xp[768 + j];
    float si = 1.f / (1.f + expf(-gi));
    float sf = 1.f / (1.f + expf(-gf));
    float so = 1.f / (1.f + expf(-go));
    float tg = tanhf(gg);
    float cn = sf * c[b * Hd + j] + si * tg;
    float hn = so * tanhf(cn);
    c[b * Hd + j] = cn;
    h[b * Hd + j] = hn;
}

// ---------------- host launcher ----------------
extern "C" void kernel_launch(void* const* d_in, const int* in_sizes, int n_in,
                              void* d_out, int out_size)
{
    const int*   x_ids = (const int*)d_in[0];
    const int*   ei    = (const int*)d_in[1];
    const int*   batch = (const int*)d_in[2];
    const float* emb   = (const float*)d_in[3];
    const float* W1    = (const float*)d_in[4];
    const float* attS1 = (const float*)d_in[5];
    const float* attD1 = (const float*)d_in[6];
    const float* b1    = (const float*)d_in[7];
    const float* W2    = (const float*)d_in[8];
    const float* attS2 = (const float*)d_in[9];
    const float* attD2 = (const float*)d_in[10];
    const float* b2    = (const float*)d_in[11];
    const float* Wih   = (const float*)d_in[12];
    const float* Whh   = (const float*)d_in[13];
    const float* bih   = (const float*)d_in[14];
    const float* bhh   = (const float*)d_in[15];
    const float* Wp    = (const float*)d_in[16];
    const float* bp    = (const float*)d_in[17];
    float* out = (float*)d_out;

    void* p;
    cudaGetSymbolAddress(&p, g_x0);      float* x0   = (float*)p;
    cudaGetSymbolAddress(&p, g_h1);      float* h1   = (float*)p;
    cudaGetSymbolAddress(&p, g_x1);      float* x1   = (float*)p;
    cudaGetSymbolAddress(&p, g_h2);      float* h2   = (float*)p;
    cudaGetSymbolAddress(&p, g_out2);    float* out2 = (float*)p;
    cudaGetSymbolAddress(&p, g_xg);      float* xg   = (float*)p;
    cudaGetSymbolAddress(&p, g_as1);     float* as1  = (float*)p;
    cudaGetSymbolAddress(&p, g_ad1);     float* ad1  = (float*)p;
    cudaGetSymbolAddress(&p, g_as2);     float* as2  = (float*)p;
    cudaGetSymbolAddress(&p, g_ad2);     float* ad2  = (float*)p;
    cudaGetSymbolAddress(&p, g_counts);  int* counts = (int*)p;
    cudaGetSymbolAddress(&p, g_rowptr);  int* rowptr = (int*)p;
    cudaGetSymbolAddress(&p, g_cursor);  int* cursor = (int*)p;
    cudaGetSymbolAddress(&p, g_colsrc);  int* colsrc = (int*)p;
    cudaGetSymbolAddress(&p, g_len);     int* len    = (int*)p;
    cudaGetSymbolAddress(&p, g_starts);  int* starts = (int*)p;
    cudaGetSymbolAddress(&p, g_nodeidx); int* nodeidx= (int*)p;
    cudaGetSymbolAddress(&p, g_gbuf);    float* gbuf = (float*)p;
    cudaGetSymbolAddress(&p, g_h);       float* hS   = (float*)p;
    cudaGetSymbolAddress(&p, g_c);       float* cS   = (float*)p;
    cudaGetSymbolAddress(&p, g_bsum);    float* bsum = (float*)p;

    // 1) embedding gather (with emb[0] := 0)
    k_gather_x0<<<Nn, Hd>>>(x_ids, emb, x0);

    // 2) h1 = x0 @ W1   (16384 x 2048 x 256), NN
    k_sgemm<128, 128, 8, 8, 8, false>
        <<<dim3(F1 / 128, Nn / 128), 256>>>(x0, W1, h1, Nn, F1, Hd, nullptr);

    // 3) per-node attention logits (layer 1)
    k_alpha1<<<Nn, 256>>>(h1, attS1, attD1, as1, ad1);

    // 4) CSR by dst (edges + self loops)
    k_init_counts<<<Nn / 256, 256>>>(counts);
    k_count_edges<<<Ee / 256, 256>>>(ei, counts);
    k_scan16k<<<1, 1024>>>(counts, rowptr);
    k_copy_cursor<<<Nn / 256, 256>>>(rowptr, cursor);
    k_scatter_edges<<<Ee / 256, 256>>>(ei, cursor, colsrc);
    k_scatter_loops<<<Nn / 256, 256>>>(cursor, colsrc);

    // 5) GAT1 softmax-aggregate + b1 + ELU -> x1
    k_gat1_agg<<<Nn, 256>>>(h1, as1, ad1, rowptr, colsrc, b1, x1);

    // 6) h2 = x1 @ W2   (16384 x 256 x 2048), NN
    k_sgemm<128, 128, 8, 8, 8, false>
        <<<dim3(Hd / 128, Nn / 128), 256>>>(x1, W2, h2, Nn, Hd, F1, nullptr);

    // 7) layer-2 attention logits
    k_alpha2<<<Nn, 256>>>(h2, attS2, attD2, as2, ad2);

    // 8) GAT2 aggregate + b2 -> out2
    k_gat2_agg<<<Nn, 256>>>(h2, as2, ad2, rowptr, colsrc, b2, out2);

    // 9) sequence bookkeeping
    k_zero_len<<<1, Bsz>>>(len);
    k_count_len<<<Nn / 256, 256>>>(batch, len);
    k_scan256<<<1, Bsz>>>(len, starts);
    k_nodeidx<<<Nn / 256, 256>>>(batch, starts, nodeidx);
    k_bsum<<<G4 / 256, 256>>>(bih, bhh, bsum);

    // 10) xg = out2 @ Wih^T + (bih + bhh)   (16384 x 1024 x 256), NT
    k_sgemm<128, 128, 8, 8, 8, true>
        <<<dim3(G4 / 128, Nn / 128), 256>>>(out2, Wih, xg, Nn, G4, Hd, bsum);

    // 11) LSTM over 64 steps: g = h_prev @ Whh^T, then fused gates
    k_zero_hc<<<(Bsz * Hd) / 256, 256>>>(hS, cS);
    for (int t = 0; t < Lseq; t++) {
        k_sgemm<32, 64, 16, 4, 4, true>
            <<<dim3(G4 / 64, Bsz / 32), 128>>>(hS, Whh, gbuf, Bsz, G4, Hd, nullptr);
        k_gate<<<Bsz, Hd>>>(gbuf, xg, nodeidx, len, hS, cS, t);
    }

    // 12) out = hT @ Wp^T + bp   (256 x 37000 x 256), NT with N guard
    k_sgemm<128, 128, 8, 8, 8, true>
        <<<dim3((NNODE_ + 127) / 128, Bsz / 128), 256>>>(hS, Wp, out, Bsz, NNODE_, Hd, bp);
}

// round 5
// speedup vs baseline: 1.1072x; 1.1072x over previous
#include <cuda_runtime.h>
#include <math.h>

// ---------------- problem constants (fixed by setup_inputs) ----------------
#define Nn      16384       // nodes = B*L
#define Ee      131072      // edges (without self loops)
#define ETOT    (Ee + Nn)   // with self loops
#define Bsz     256         // batch
#define Lseq    64
#define Hd      256
#define NHEADS  8
#define F1      2048        // HEADS*H
#define G4      1024        // 4*H
#define NNODE_  37000

#define LSTM_BLOCKS 128

// ---------------- device scratch (static, allocation-free) ----------------
__device__ float g_x0  [(size_t)Nn * Hd];
__device__ float g_h1  [(size_t)Nn * F1];
__device__ float g_x1  [(size_t)Nn * F1];
__device__ float g_h2  [(size_t)Nn * Hd];
__device__ float g_out2[(size_t)Nn * Hd];
__device__ float g_xg  [(size_t)Nn * G4];
__device__ float g_as1 [Nn * NHEADS];
__device__ float g_ad1 [Nn * NHEADS];
__device__ float g_as2 [Nn];
__device__ float g_ad2 [Nn];
__device__ int   g_counts[Nn];
__device__ int   g_rowptr[Nn + 1];
__device__ int   g_cursor[Nn];
__device__ int   g_colsrc[ETOT];
__device__ int   g_len   [Bsz];
__device__ int   g_starts[Bsz];
__device__ int   g_nodeidx[Bsz * Lseq];
__device__ float g_hbuf1[Bsz * Hd];     // LSTM h double-buffer (odd)
__device__ float g_h    [Bsz * Hd];     // LSTM h double-buffer (even) + final hT
__device__ float g_bsum [G4];
__device__ unsigned g_bar_arrive = 0;   // grid barrier state (self-resetting)
__device__ unsigned g_bar_gen    = 0;

// ---------------- double-buffered tiled SGEMM ----------------
// C[M,N] = A[M,K] @ op(B) (+ bias[n])
// BT=false: B row-major [K,N].  BT=true: B row-major [N,K] (C = A @ B^T).
// M % BM == 0, K % BK == 0.  N-edge guarded (needed for N = 37000).
template<int BM, int BN, int BK, int TM, int TN, bool BT>
__global__ void __launch_bounds__((BM / TM) * (BN / TN))
k_sgemm(const float* __restrict__ A, const float* __restrict__ B,
        float* __restrict__ C, int M, int N, int K,
        const float* __restrict__ bias)
{
    constexpr int THREADS = (BM / TM) * (BN / TN);
    constexpr int TX = BN / TN;
    constexpr int LA = BM * BK / 4 / THREADS;   // float4 loads / thread (A)
    constexpr int LB = BN * BK / 4 / THREADS;   // float4 loads / thread (B)

    __shared__ float As[2][BK][BM + 4];
    __shared__ float Bs[2][BK][BN + 4];

    const int tid = threadIdx.x;
    const int bm  = blockIdx.y * BM;
    const int bn  = blockIdx.x * BN;
    const int tx  = tid % TX;
    const int ty  = tid / TX;

    float acc[TM][TN];
#pragma unroll
    for (int i = 0; i < TM; i++)
#pragma unroll
        for (int j = 0; j < TN; j++) acc[i][j] = 0.f;

    float4 ra[LA], rb[LB];

    // ---- fetch tile kt into registers ----
    auto fetchA = [&](int kt) {
#pragma unroll
        for (int l = 0; l < LA; l++) {
            int off = (tid + l * THREADS) * 4;
            int r = off / BK, cc = off % BK;
            ra[l] = *reinterpret_cast<const float4*>(
                &A[(size_t)(bm + r) * K + kt * BK + cc]);
        }
    };
    auto fetchB = [&](int kt) {
        if (BT) {
#pragma unroll
            for (int l = 0; l < LB; l++) {
                int off = (tid + l * THREADS) * 4;
                int r = off / BK, cc = off % BK;
                if (bn + r < N)
                    rb[l] = *reinterpret_cast<const float4*>(
                        &B[(size_t)(bn + r) * K + kt * BK + cc]);
                else
                    rb[l] = make_float4(0.f, 0.f, 0.f, 0.f);
            }
        } else {
#pragma unroll
            for (int l = 0; l < LB; l++) {
                int off = (tid + l * THREADS) * 4;
                int r = off / BN, cc = off % BN;
                rb[l] = *reinterpret_cast<const float4*>(
                    &B[(size_t)(kt * BK + r) * N + bn + cc]);
            }
        }
    };
    auto storeA = [&](int b) {
#pragma unroll
        for (int l = 0; l < LA; l++) {
            int off = (tid + l * THREADS) * 4;
            int r = off / BK, cc = off % BK;
            As[b][cc + 0][r] = ra[l].x; As[b][cc + 1][r] = ra[l].y;
            As[b][cc + 2][r] = ra[l].z; As[b][cc + 3][r] = ra[l].w;
        }
    };
    auto storeB = [&](int b) {
        if (BT) {
#pragma unroll
            for (int l = 0; l < LB; l++) {
                int off = (tid + l * THREADS) * 4;
                int r = off / BK, cc = off % BK;
                Bs[b][cc + 0][r] = rb[l].x; Bs[b][cc + 1][r] = rb[l].y;
                Bs[b][cc + 2][r] = rb[l].z; Bs[b][cc + 3][r] = rb[l].w;
            }
        } else {
#pragma unroll
            for (int l = 0; l < LB; l++) {
                int off = (tid + l * THREADS) * 4;
                int r = off / BN, cc = off % BN;
                *reinterpret_cast<float4*>(&Bs[b][r][cc]) = rb[l];
            }
        }
    };

    const int nt = K / BK;
    fetchA(0); fetchB(0);
    storeA(0); storeB(0);
    __syncthreads();

    int buf = 0;
    for (int kt = 0; kt < nt; kt++) {
        if (kt + 1 < nt) { fetchA(kt + 1); fetchB(kt + 1); }
#pragma unroll
        for (int kk = 0; kk < BK; kk++) {
            float af[TM], bf[TN];
#pragma unroll
            for (int i = 0; i < TM; i++) af[i] = As[buf][kk][ty * TM + i];
#pragma unroll
            for (int j = 0; j < TN; j++) bf[j] = Bs[buf][kk][tx * TN + j];
#pragma unroll
            for (int i = 0; i < TM; i++)
#pragma unroll
                for (int j = 0; j < TN; j++) acc[i][j] += af[i] * bf[j];
        }
        if (kt + 1 < nt) { storeA(buf ^ 1); storeB(buf ^ 1); }
        __syncthreads();
        buf ^= 1;
    }

    // --- store with N guard + optional bias ---
#pragma unroll
    for (int i = 0; i < TM; i++) {
        int row = bm + ty * TM + i;
#pragma unroll
        for (int j = 0; j < TN; j += 4) {
            int col = bn + tx * TN + j;
            if (col + 3 < N) {
                float4 v;
                v.x = acc[i][j + 0] + (bias ? bias[col + 0] : 0.f);
                v.y = acc[i][j + 1] + (bias ? bias[col + 1] : 0.f);
                v.z = acc[i][j + 2] + (bias ? bias[col + 2] : 0.f);
                v.w = acc[i][j + 3] + (bias ? bias[col + 3] : 0.f);
                *reinterpret_cast<float4*>(&C[(size_t)row * N + col]) = v;
            } else {
#pragma unroll
                for (int u = 0; u < 4; u++) {
                    if (col + u < N)
                        C[(size_t)row * N + col + u] =
                            acc[i][j + u] + (bias ? bias[col + u] : 0.f);
                }
            }
        }
    }
}

// ---------------- embedding gather (emb[0] := 0) ----------------
__global__ void k_gather_x0(const int* __restrict__ ids,
                            const float* __restrict__ emb,
                            float* __restrict__ x0)
{
    int i = blockIdx.x, t = threadIdx.x;
    int id = ids[i];
    x0[(size_t)i * Hd + t] = (id == 0) ? 0.f : emb[(size_t)id * Hd + t];
}

// ---------------- attention logits ----------------
__global__ void k_alpha1(const float* __restrict__ h1,
                         const float* __restrict__ attS,
                         const float* __restrict__ attD,
                         float* __restrict__ outS, float* __restrict__ outD)
{
    int i = blockIdx.x;
    int w = threadIdx.x >> 5, lane = threadIdx.x & 31;
    const float* hp = h1 + (size_t)i * F1 + w * Hd;
    const float* ap = attS + w * Hd;
    const float* dp = attD + w * Hd;
    float ss = 0.f, sd = 0.f;
#pragma unroll
    for (int u = 0; u < 8; u++) {
        float v = hp[lane + 32 * u];
        ss += v * ap[lane + 32 * u];
        sd += v * dp[lane + 32 * u];
    }
#pragma unroll
    for (int o = 16; o; o >>= 1) {
        ss += __shfl_xor_sync(0xffffffffu, ss, o);
        sd += __shfl_xor_sync(0xffffffffu, sd, o);
    }
    if (lane == 0) { outS[i * NHEADS + w] = ss; outD[i * NHEADS + w] = sd; }
}

__global__ void k_alpha2(const float* __restrict__ h2,
                         const float* __restrict__ attS,
                         const float* __restrict__ attD,
                         float* __restrict__ outS, float* __restrict__ outD)
{
    __shared__ float shS[8], shD[8];
    int i = blockIdx.x, t = threadIdx.x;
    float v = h2[(size_t)i * Hd + t];
    float ss = v * attS[t], sd = v * attD[t];
    int lane = t & 31, w = t >> 5;
#pragma unroll
    for (int o = 16; o; o >>= 1) {
        ss += __shfl_xor_sync(0xffffffffu, ss, o);
        sd += __shfl_xor_sync(0xffffffffu, sd, o);
    }
    if (lane == 0) { shS[w] = ss; shD[w] = sd; }
    __syncthreads();
    if (t == 0) {
        float a = 0.f, b = 0.f;
#pragma unroll
        for (int u = 0; u < 8; u++) { a += shS[u]; b += shD[u]; }
        outS[i] = a; outD[i] = b;
    }
}

// ---------------- CSR build (group edges by dst) ----------------
__global__ void k_init_counts(int* __restrict__ counts)
{
    int i = blockIdx.x * blockDim.x + threadIdx.x;
    if (i < Nn) counts[i] = 1;
}
__global__ void k_count_edges(const int* __restrict__ ei, int* __restrict__ counts)
{
    int e = blockIdx.x * blockDim.x + threadIdx.x;
    if (e < Ee) atomicAdd(&counts[ei[Ee + e]], 1);
}
__global__ void k_scan16k(const int* __restrict__ counts, int* __restrict__ rowptr)
{
    __shared__ int wsum[32];
    const int tid = threadIdx.x;
    const int per = Nn / 1024;
    const int base = tid * per;
    int c[16];
    int tot = 0;
#pragma unroll
    for (int u = 0; u < per; u++) { c[u] = counts[base + u]; tot += c[u]; }
    int lane = tid & 31, wid = tid >> 5;
    int v = tot;
#pragma unroll
    for (int o = 1; o < 32; o <<= 1) {
        int t2 = __shfl_up_sync(0xffffffffu, v, o);
        if (lane >= o) v += t2;
    }
    if (lane == 31) wsum[wid] = v;
    __syncthreads();
    if (wid == 0) {
        int w = wsum[lane];
#pragma unroll
        for (int o = 1; o < 32; o <<= 1) {
            int t2 = __shfl_up_sync(0xffffffffu, w, o);
            if (lane >= o) w += t2;
        }
        wsum[lane] = w;
    }
    __syncthreads();
    int run = (v - tot) + (wid > 0 ? wsum[wid - 1] : 0);
#pragma unroll
    for (int u = 0; u < per; u++) { rowptr[base + u] = run; run += c[u]; }
    if (tid == 1023) rowptr[Nn] = run;
}
__global__ void k_copy_cursor(const int* __restrict__ rowptr, int* __restrict__ cursor)
{
    int i = blockIdx.x * blockDim.x + threadIdx.x;
    if (i < Nn) cursor[i] = rowptr[i];
}
__global__ void k_scatter_edges(const int* __restrict__ ei,
                                int* __restrict__ cursor, int* __restrict__ colsrc)
{
    int e = blockIdx.x * blockDim.x + threadIdx.x;
    if (e < Ee) {
        int d = ei[Ee + e];
        int p = atomicAdd(&cursor[d], 1);
        colsrc[p] = ei[e];
    }
}
__global__ void k_scatter_loops(int* __restrict__ cursor, int* __restrict__ colsrc)
{
    int i = blockIdx.x * blockDim.x + threadIdx.x;
    if (i < Nn) {
        int p = atomicAdd(&cursor[i], 1);
        colsrc[p] = i;
    }
}

// ---------------- GAT aggregation ----------------
__global__ void k_gat1_agg(const float* __restrict__ h1,
                           const float* __restrict__ aS, const float* __restrict__ aD,
                           const int* __restrict__ rowptr, const int* __restrict__ colsrc,
                           const float* __restrict__ b1, float* __restrict__ x1)
{
    int dst = blockIdx.x;
    int w = threadIdx.x >> 5, lane = threadIdx.x & 31;
    int beg = rowptr[dst], end = rowptr[dst + 1];
    float adv = aD[dst * NHEADS + w];

    float m = -3.4e38f;
    for (int e = beg; e < end; e++) {
        float v = aS[colsrc[e] * NHEADS + w] + adv;
        v = v > 0.f ? v : 0.2f * v;
        m = fmaxf(m, v);
    }
    float acc[8] = {0.f, 0.f, 0.f, 0.f, 0.f, 0.f, 0.f, 0.f};
    float sump = 0.f;
    for (int e = beg; e < end; e++) {
        int s = colsrc[e];
        float v = aS[s * NHEADS + w] + adv;
        v = v > 0.f ? v : 0.2f * v;
        float p = expf(v - m);
        sump += p;
        const float* hp = h1 + (size_t)s * F1 + w * Hd + lane;
#pragma unroll
        for (int u = 0; u < 8; u++) acc[u] += p * hp[u * 32];
    }
    float inv = 1.f / (sump + 1e-16f);
    float* xp = x1 + (size_t)dst * F1 + w * Hd + lane;
    const float* bp = b1 + w * Hd + lane;
#pragma unroll
    for (int u = 0; u < 8; u++) {
        float o = acc[u] * inv + bp[u * 32];
        xp[u * 32] = o > 0.f ? o : expm1f(o);   // ELU
    }
}

__global__ void k_gat2_agg(const float* __restrict__ h2,
                           const float* __restrict__ aS, const float* __restrict__ aD,
                           const int* __restrict__ rowptr, const int* __restrict__ colsrc,
                           const float* __restrict__ b2, float* __restrict__ out2)
{
    int dst = blockIdx.x, t = threadIdx.x;
    int beg = rowptr[dst], end = rowptr[dst + 1];
    float adv = aD[dst];
    float m = -3.4e38f;
    for (int e = beg; e < end; e++) {
        float v = aS[colsrc[e]] + adv;
        v = v > 0.f ? v : 0.2f * v;
        m = fmaxf(m, v);
    }
    float acc = 0.f, sump = 0.f;
    for (int e = beg; e < end; e++) {
        int s = colsrc[e];
        float v = aS[s] + adv;
        v = v > 0.f ? v : 0.2f * v;
        float p = expf(v - m);
        sump += p;
        acc += p * h2[(size_t)s * Hd + t];
    }
    out2[(size_t)dst * Hd + t] = acc / (sump + 1e-16f) + b2[t];
}

// ---------------- sequence bookkeeping ----------------
__global__ void k_zero_len(int* __restrict__ len) { len[threadIdx.x] = 0; }
__global__ void k_count_len(const int* __restrict__ batch, int* __restrict__ len)
{
    int i = blockIdx.x * blockDim.x + threadIdx.x;
    if (i < Nn) atomicAdd(&len[batch[i]], 1);
}
__global__ void k_scan256(const int* __restrict__ len, int* __restrict__ starts)
{
    __shared__ int wsum[8];
    int tid = threadIdx.x;
    int orig = len[tid];
    int v = orig;
    int lane = tid & 31, wid = tid >> 5;
#pragma unroll
    for (int o = 1; o < 32; o <<= 1) {
        int t2 = __shfl_up_sync(0xffffffffu, v, o);
        if (lane >= o) v += t2;
    }
    if (lane == 31) wsum[wid] = v;
    __syncthreads();
    if (tid == 0) {
        int s = 0;
#pragma unroll
        for (int u = 0; u < 8; u++) { int t2 = wsum[u]; wsum[u] = s; s += t2; }
    }
    __syncthreads();
    starts[tid] = (v - orig) + wsum[wid];
}
__global__ void k_nodeidx(const int* __restrict__ batch, const int* __restrict__ starts,
                          int* __restrict__ nodeidx)
{
    int i = blockIdx.x * blockDim.x + threadIdx.x;
    if (i < Nn) {
        int b = batch[i];
        int p = i - starts[b];
        if (p >= 0 && p < Lseq) nodeidx[b * Lseq + p] = i;
    }
}
__global__ void k_bsum(const float* __restrict__ bih, const float* __restrict__ bhh,
                       float* __restrict__ bs)
{
    int k = blockIdx.x * blockDim.x + threadIdx.x;
    if (k < G4) bs[k] = bih[k] + bhh[k];
}
__global__ void k_zero_h(float* __restrict__ h)
{
    int i = blockIdx.x * blockDim.x + threadIdx.x;
    h[i] = 0.f;
}

// ---------------- persistent fused LSTM (all 64 steps, 1 launch) ----------------
// grid = 128 blocks (<= 148 SMs, 1 block/SM via smem => all wave-1 resident).
// block (jb = bx%16, mb = bx/16): hidden slice jb*16..+16, batch tile mb*32..+32.
// Whh slice (64 gate rows) cached transposed in SMEM for all 64 steps.
// h double-buffered through global memory (.cg = L1 bypass), c kept in SMEM.
#define WST 68   // WshT row stride (words), mult of 4, bank-friendly
__global__ void __launch_bounds__(256, 1)
k_lstm(const float* __restrict__ xg, const int* __restrict__ nodeidx,
       const int* __restrict__ len, float* __restrict__ hbuf0,
       float* __restrict__ hbuf1, const float* __restrict__ Whh)
{
    extern __shared__ float sm[];
    float* WshT = sm;                       // [256][WST] (rows: k, cols: 64 local gate rows)
    float* HshT = sm + 256 * WST;           // [256][33]  (rows: k=hidden, cols: 32 batches)
    float* red  = HshT + 256 * 33;          // [4][64][33] k-split partials
    float* csh  = red + 4 * 64 * 33;        // [16][32] cell state

    const int tid  = threadIdx.x;
    const int jb   = blockIdx.x & 15;
    const int mb   = blockIdx.x >> 4;
    const int kg   = tid >> 6;              // k-group 0..3
    const int t64  = tid & 63;
    const int rowq = t64 & 15;              // owns local rows rowq*4..+3
    const int bq   = t64 >> 4;              // owns batches bq*8..+7

    // snapshot barrier generation (safe: gen can't advance until THIS block arrives)
    unsigned my_gen = atomicAdd(&g_bar_gen, 0u);

    // one-time: load Whh slice transposed. local row r = g*16+u  <->  global row g*256 + jb*16 + u
    for (int idx = tid; idx < 64 * 256; idx += 256) {
        int r = idx >> 8;                   // 0..63
        int k = idx & 255;
        int g = r >> 4, u = r & 15;
        WshT[k * WST + r] = Whh[(size_t)(g * 256 + jb * 16 + u) * 256 + k];
    }
    if (tid < 256) { csh[tid & 511] = 0.f; if (tid + 256 < 512) csh[tid + 256] = 0.f; }

    for (int t = 0; t < Lseq; t++) {
        // ---- load h_cur tile into SMEM (transposed), L1-bypassed ----
        const float* hc = (t & 1) ? hbuf1 : hbuf0;
#pragma unroll
        for (int l = 0; l < 32; l++) {
            int idx = tid + l * 256;
            int bl = idx >> 8, k = idx & 255;
            HshT[k * 33 + bl] = __ldcg(&hc[(mb * 32 + bl) * 256 + k]);
        }
        __syncthreads();

        // ---- k-split GEMM: gate[r][b] partials over k in [kg*64, kg*64+64) ----
        float acc[4][8];
#pragma unroll
        for (int i = 0; i < 4; i++)
#pragma unroll
            for (int j = 0; j < 8; j++) acc[i][j] = 0.f;
        const int k0 = kg * 64;
#pragma unroll 4
        for (int k = k0; k < k0 + 64; k++) {
            float4 w = *reinterpret_cast<const float4*>(&WshT[k * WST + rowq * 4]);
            const float* hr = &HshT[k * 33 + bq * 8];
#pragma unroll
            for (int j = 0; j < 8; j++) {
                float hv = hr[j];
                acc[0][j] += w.x * hv;
                acc[1][j] += w.y * hv;
                acc[2][j] += w.z * hv;
                acc[3][j] += w.w * hv;
            }
        }
#pragma unroll
        for (int i = 0; i < 4; i++)
#pragma unroll
            for (int j = 0; j < 8; j++)
                red[kg * (64 * 33) + (rowq * 4 + i) * 33 + bq * 8 + j] = acc[i][j];
        __syncthreads();

        // ---- combine 4 partials + xg, apply gates, update c (smem) & h (global) ----
        float* hn_buf = (t & 1) ? hbuf0 : hbuf1;
#pragma unroll
        for (int p = tid; p < 512; p += 256) {
            int u = p & 15;                 // local hidden index
            int bl = p >> 4;                // local batch
            int bglob = mb * 32 + bl;
            int node = nodeidx[bglob * Lseq + t];
            const float* xp = xg + (size_t)node * G4 + jb * 16 + u;
            float gi = 0.f, gf = 0.f, gg = 0.f, go = 0.f;
#pragma unroll
            for (int q = 0; q < 4; q++) {
                const float* rq = red + q * (64 * 33);
                gi += rq[(0 * 16 + u) * 33 + bl];
                gf += rq[(1 * 16 + u) * 33 + bl];
                gg += rq[(2 * 16 + u) * 33 + bl];
                go += rq[(3 * 16 + u) * 33 + bl];
            }
            gi += xp[0]; gf += xp[256]; gg += xp[512]; go += xp[768];
            float hprev = HshT[(jb * 16 + u) * 33 + bl];
            float cprev = csh[u * 32 + bl];
            float si = 1.f / (1.f + expf(-gi));
            float sf = 1.f / (1.f + expf(-gf));
            float so = 1.f / (1.f + expf(-go));
            float cn = sf * cprev + si * tanhf(gg);
            float hn = so * tanhf(cn);
            bool act = (t < len[bglob]);
            if (act) csh[u * 32 + bl] = cn;
            float hw = act ? hn : hprev;
            __stcg(&hn_buf[bglob * 256 + jb * 16 + u], hw);
        }

        // ---- grid barrier (skip after last step) ----
        if (t != Lseq - 1) {
            __threadfence();
            __syncthreads();
            if (tid == 0) {
                unsigned old = atomicAdd(&g_bar_arrive, 1u);
                if (old == LSTM_BLOCKS - 1) {
                    atomicExch(&g_bar_arrive, 0u);
                    __threadfence();
                    atomicAdd(&g_bar_gen, 1u);
                } else {
                    while (atomicAdd(&g_bar_gen, 0u) == my_gen) __nanosleep(64);
                }
            }
            __syncthreads();
            my_gen++;
        }
    }
    // final hT (t=63 odd) was written to hbuf0 == g_h
}

// ---------------- host launcher ----------------
extern "C" void kernel_launch(void* const* d_in, const int* in_sizes, int n_in,
                              void* d_out, int out_size)
{
    const int*   x_ids = (const int*)d_in[0];
    const int*   ei    = (const int*)d_in[1];
    const int*   batch = (const int*)d_in[2];
    const float* emb   = (const float*)d_in[3];
    const float* W1    = (const float*)d_in[4];
    const float* attS1 = (const float*)d_in[5];
    const float* attD1 = (const float*)d_in[6];
    const float* b1    = (const float*)d_in[7];
    const float* W2    = (const float*)d_in[8];
    const float* attS2 = (const float*)d_in[9];
    const float* attD2 = (const float*)d_in[10];
    const float* b2    = (const float*)d_in[11];
    const float* Wih   = (const float*)d_in[12];
    const float* Whh   = (const float*)d_in[13];
    const float* bih   = (const float*)d_in[14];
    const float* bhh   = (const float*)d_in[15];
    const float* Wp    = (const float*)d_in[16];
    const float* bp    = (const float*)d_in[17];
    float* out = (float*)d_out;

    void* p;
    cudaGetSymbolAddress(&p, g_x0);      float* x0   = (float*)p;
    cudaGetSymbolAddress(&p, g_h1);      float* h1   = (float*)p;
    cudaGetSymbolAddress(&p, g_x1);      float* x1   = (float*)p;
    cudaGetSymbolAddress(&p, g_h2);      float* h2   = (float*)p;
    cudaGetSymbolAddress(&p, g_out2);    float* out2 = (float*)p;
    cudaGetSymbolAddress(&p, g_xg);      float* xg   = (float*)p;
    cudaGetSymbolAddress(&p, g_as1);     float* as1  = (float*)p;
    cudaGetSymbolAddress(&p, g_ad1);     float* ad1  = (float*)p;
    cudaGetSymbolAddress(&p, g_as2);     float* as2  = (float*)p;
    cudaGetSymbolAddress(&p, g_ad2);     float* ad2  = (float*)p;
    cudaGetSymbolAddress(&p, g_counts);  int* counts = (int*)p;
    cudaGetSymbolAddress(&p, g_rowptr);  int* rowptr = (int*)p;
    cudaGetSymbolAddress(&p, g_cursor);  int* cursor = (int*)p;
    cudaGetSymbolAddress(&p, g_colsrc);  int* colsrc = (int*)p;
    cudaGetSymbolAddress(&p, g_len);     int* len    = (int*)p;
    cudaGetSymbolAddress(&p, g_starts);  int* starts = (int*)p;
    cudaGetSymbolAddress(&p, g_nodeidx); int* nodeidx= (int*)p;
    cudaGetSymbolAddress(&p, g_hbuf1);   float* hb1  = (float*)p;
    cudaGetSymbolAddress(&p, g_h);       float* hS   = (float*)p;
    cudaGetSymbolAddress(&p, g_bsum);    float* bsum = (float*)p;

    // LSTM smem: (256*68 + 256*33 + 4*64*33 + 512) floats
    static const int LSTM_SMEM = (256 * WST + 256 * 33 + 4 * 64 * 33 + 512) * 4;
    cudaFuncSetAttribute(k_lstm, cudaFuncAttributeMaxDynamicSharedMemorySize, LSTM_SMEM);

    // 1) embedding gather (with emb[0] := 0)
    k_gather_x0<<<Nn, Hd>>>(x_ids, emb, x0);

    // 2) h1 = x0 @ W1   (16384 x 2048 x 256), NN
    k_sgemm<128, 128, 16, 8, 8, false>
        <<<dim3(F1 / 128, Nn / 128), 256>>>(x0, W1, h1, Nn, F1, Hd, nullptr);

    // 3) per-node attention logits (layer 1)
    k_alpha1<<<Nn, 256>>>(h1, attS1, attD1, as1, ad1);

    // 4) CSR by dst (edges + self loops)
    k_init_counts<<<Nn / 256, 256>>>(counts);
    k_count_edges<<<Ee / 256, 256>>>(ei, counts);
    k_scan16k<<<1, 1024>>>(counts, rowptr);
    k_copy_cursor<<<Nn / 256, 256>>>(rowptr, cursor);
    k_scatter_edges<<<Ee / 256, 256>>>(ei, cursor, colsrc);
    k_scatter_loops<<<Nn / 256, 256>>>(cursor, colsrc);

    // 5) GAT1 softmax-aggregate + b1 + ELU -> x1
    k_gat1_agg<<<Nn, 256>>>(h1, as1, ad1, rowptr, colsrc, b1, x1);

    // 6) h2 = x1 @ W2   (16384 x 256 x 2048), NN
    k_sgemm<128, 128, 16, 8, 8, false>
        <<<dim3(Hd / 128, Nn / 128), 256>>>(x1, W2, h2, Nn, Hd, F1, nullptr);

    // 7) layer-2 attention logits
    k_alpha2<<<Nn, 256>>>(h2, attS2, attD2, as2, ad2);

    // 8) GAT2 aggregate + b2 -> out2
    k_gat2_agg<<<Nn, 256>>>(h2, as2, ad2, rowptr, colsrc, b2, out2);

    // 9) sequence bookkeeping
    k_zero_len<<<1, Bsz>>>(len);
    k_count_len<<<Nn / 256, 256>>>(batch, len);
    k_scan256<<<1, Bsz>>>(len, starts);
    k_nodeidx<<<Nn / 256, 256>>>(batch, starts, nodeidx);
    k_bsum<<<G4 / 256, 256>>>(bih, bhh, bsum);

    // 10) xg = out2 @ Wih^T + (bih + bhh)   (16384 x 1024 x 256), NT
    k_sgemm<128, 128, 16, 8, 8, true>
        <<<dim3(G4 / 128, Nn / 128), 256>>>(out2, Wih, xg, Nn, G4, Hd, bsum);

    // 11) persistent fused LSTM: all 64 steps in ONE launch
    k_zero_h<<<(Bsz * Hd) / 256, 256>>>(hS);
    k_lstm<<<LSTM_BLOCKS, 256, LSTM_SMEM>>>(xg, nodeidx, len, hS, hb1, Whh);

    // 12) out = hT @ Wp^T + bp   (256 x 37000 x 256), NT with N guard
    k_sgemm<128, 128, 16, 8, 8, true>
        <<<dim3((NNODE_ + 127) / 128, Bsz / 128), 256>>>(hS, Wp, out, Bsz, NNODE_, Hd, bp);
}

// round 7
// speedup vs baseline: 1.7377x; 1.5694x over previous
#include <cuda_runtime.h>
#include <cuda_bf16.h>
#include <stdint.h>
#include <math.h>

typedef unsigned int u32;

// ---------------- problem constants ----------------
#define Nn      16384
#define Ee      131072
#define ETOT    (Ee + Nn)
#define Bsz     256
#define Lseq    64
#define Hd      256
#define NHEADS  8
#define F1      2048
#define G4      1024
#define NNODE_  37000

#define LSTM_BLOCKS 128

// ---------------- device scratch ----------------
__device__ float g_h1  [(size_t)Nn * F1];
__device__ float g_h2  [(size_t)Nn * Hd];
__device__ float g_xg  [(size_t)Nn * G4];
__device__ float g_as1 [Nn * NHEADS];
__device__ float g_ad1 [Nn * NHEADS];
__device__ float g_as2 [Nn];
__device__ float g_ad2 [Nn];
__device__ int   g_counts[Nn];
__device__ int   g_rowptr[Nn + 1];
__device__ int   g_cursor[Nn];
__device__ int   g_colsrc[ETOT];
__device__ int   g_len   [Bsz];
__device__ int   g_starts[Bsz];
__device__ int   g_nodeidx[Bsz * Lseq];
__device__ float g_hbuf1[Bsz * Hd];
__device__ float g_h    [Bsz * Hd];
__device__ float g_bsum [G4];
__device__ unsigned g_bar_arrive = 0;
__device__ unsigned g_bar_gen    = 0;

// bf16 hi/lo split operands for tensor-core GEMMs
__device__ __nv_bfloat16 g_x0h[(size_t)Nn * Hd],  g_x0l[(size_t)Nn * Hd];
__device__ __nv_bfloat16 g_x1h[(size_t)Nn * F1],  g_x1l[(size_t)Nn * F1];
__device__ __nv_bfloat16 g_o2h[(size_t)Nn * Hd],  g_o2l[(size_t)Nn * Hd];
__device__ __nv_bfloat16 g_W1Th[(size_t)F1 * Hd], g_W1Tl[(size_t)F1 * Hd];
__device__ __nv_bfloat16 g_W2Th[(size_t)Hd * F1], g_W2Tl[(size_t)Hd * F1];
__device__ __nv_bfloat16 g_Wihh[(size_t)G4 * Hd], g_Wihl[(size_t)G4 * Hd];
__device__ __nv_bfloat16 g_hTh[Bsz * Hd],         g_hTl[Bsz * Hd];
__device__ __nv_bfloat16 g_Wph[(size_t)NNODE_ * Hd], g_Wpl[(size_t)NNODE_ * Hd];

// ---------------- small helpers ----------------
__device__ __forceinline__ void split_bf16(float v, __nv_bfloat16& h, __nv_bfloat16& l)
{
    h = __float2bfloat16(v);
    l = __float2bfloat16(v - __bfloat162float(h));
}
__device__ __forceinline__ u32 smem_u32(const void* p)
{
    return (u32)__cvta_generic_to_shared(p);
}
__device__ __forceinline__ void cp16(u32 dst, const void* src, int srcsize)
{
    asm volatile("cp.async.cg.shared.global [%0], [%1], 16, %2;"
                 :: "r"(dst), "l"(src), "r"(srcsize) : "memory");
}
__device__ __forceinline__ void cp_commit()
{
    asm volatile("cp.async.commit_group;" ::: "memory");
}
template<int NG>
__device__ __forceinline__ void cp_wait()
{
    asm volatile("cp.async.wait_group %0;" :: "n"(NG) : "memory");
}
__device__ __forceinline__ void ldsm_x4(u32 a, u32& r0, u32& r1, u32& r2, u32& r3)
{
    asm volatile("ldmatrix.sync.aligned.m8n8.x4.shared.b16 {%0,%1,%2,%3},[%4];"
                 : "=r"(r0), "=r"(r1), "=r"(r2), "=r"(r3) : "r"(a));
}
__device__ __forceinline__ void mma16816(float* c, u32 a0, u32 a1, u32 a2, u32 a3,
                                         u32 b0, u32 b1)
{
    asm volatile("mma.sync.aligned.m16n8k16.row.col.f32.bf16.bf16.f32 "
                 "{%0,%1,%2,%3},{%4,%5,%6,%7},{%8,%9},{%0,%1,%2,%3};"
                 : "+f"(c[0]), "+f"(c[1]), "+f"(c[2]), "+f"(c[3])
                 : "r"(a0), "r"(a1), "r"(a2), "r"(a3), "r"(b0), "r"(b1));
}

// ---------------- bf16x3 tensor-core GEMM ----------------
// C[M,N] = (Ah+Al)[M,K] @ (Bh+Bl)[N,K]^T + bias   (3-term product, fp32 acc)
// M % 128 == 0, K % 32 == 0 (N guarded per row).
#define GBM 128
#define GBN 128
#define GBK 32
#define BROW 40                       // smem row stride (bf16 elems)
#define ABUF (GBM * BROW)             // elems per (stage,hl) buffer
#define GEMM_SMEM (8 * ABUF * 2)      // bytes: As[2][2] + Bs[2][2]

__global__ void __launch_bounds__(256, 1)
k_gemm_bf3(const __nv_bfloat16* __restrict__ Ah, const __nv_bfloat16* __restrict__ Al,
           const __nv_bfloat16* __restrict__ Bh, const __nv_bfloat16* __restrict__ Bl,
           float* __restrict__ C, int M, int N, int K, const float* __restrict__ bias)
{
    extern __shared__ __nv_bfloat16 smg[];
    __nv_bfloat16* As = smg;              // [st][hl][128*BROW]
    __nv_bfloat16* Bs = smg + 4 * ABUF;
    const u32 sA = smem_u32(As);
    const u32 sB = smem_u32(Bs);

    const int tid  = threadIdx.x;
    const int bm   = blockIdx.y * GBM;
    const int bn   = blockIdx.x * GBN;
    const int warp = tid >> 5, lane = tid & 31;
    const int wm   = (warp >> 2) * 64;    // 2 warps along m
    const int wn   = (warp & 3) * 32;     // 4 warps along n

    float acc[4][4][4];
#pragma unroll
    for (int i = 0; i < 4; i++)
#pragma unroll
        for (int j = 0; j < 4; j++)
#pragma unroll
            for (int u = 0; u < 4; u++) acc[i][j][u] = 0.f;

    const int nstage = K / GBK;

    // ---- async stage loader: 2 chunks/thread per matrix ----
    auto loadstage = [&](int kt, int st) {
        const int k0 = kt * GBK;
#pragma unroll
        for (int l = 0; l < 2; l++) {
            int i = tid + l * 256;
            int r = i >> 2, s = (i & 3) * 8;
            u32 doffA = (u32)((r * BROW + s) * 2);
            size_t ga = (size_t)(bm + r) * K + k0 + s;
            cp16(sA + (u32)(st * 2 + 0) * (ABUF * 2) + doffA, Ah + ga, 16);
            cp16(sA + (u32)(st * 2 + 1) * (ABUF * 2) + doffA, Al + ga, 16);
            int nrow = bn + r;
            int ok = (nrow < N) ? 16 : 0;
            int nc = (nrow < N) ? nrow : (N - 1);
            size_t gb = (size_t)nc * K + k0 + s;
            cp16(sB + (u32)(st * 2 + 0) * (ABUF * 2) + doffA, Bh + gb, ok);
            cp16(sB + (u32)(st * 2 + 1) * (ABUF * 2) + doffA, Bl + gb, ok);
        }
        cp_commit();
    };

    loadstage(0, 0);
    int st = 0;
    for (int kt = 0; kt < nstage; kt++) {
        if (kt + 1 < nstage) { loadstage(kt + 1, st ^ 1); cp_wait<1>(); }
        else                 { cp_wait<0>(); }
        __syncthreads();

#pragma unroll
        for (int kk = 0; kk < 2; kk++) {
            u32 afh[4][4], afl[4][4];
#pragma unroll
            for (int mt = 0; mt < 4; mt++) {
                u32 off = (u32)(((wm + mt * 16 + (lane & 15)) * BROW
                          + kk * 16 + (lane >> 4) * 8) * 2);
                ldsm_x4(sA + (u32)(st * 2 + 0) * (ABUF * 2) + off,
                        afh[mt][0], afh[mt][1], afh[mt][2], afh[mt][3]);
                ldsm_x4(sA + (u32)(st * 2 + 1) * (ABUF * 2) + off,
                        afl[mt][0], afl[mt][1], afl[mt][2], afl[mt][3]);
            }
            u32 bfh[4][2], bfl[4][2];
#pragma unroll
            for (int half = 0; half < 2; half++) {
                int g = lane >> 3;
                u32 off = (u32)(((wn + half * 16 + (g & 1) * 8 + (lane & 7)) * BROW
                          + kk * 16 + (g >> 1) * 8) * 2);
                u32 r0, r1, r2, r3;
                ldsm_x4(sB + (u32)(st * 2 + 0) * (ABUF * 2) + off, r0, r1, r2, r3);
                bfh[half * 2 + 0][0] = r0; bfh[half * 2 + 1][0] = r1;
                bfh[half * 2 + 0][1] = r2; bfh[half * 2 + 1][1] = r3;
                ldsm_x4(sB + (u32)(st * 2 + 1) * (ABUF * 2) + off, r0, r1, r2, r3);
                bfl[half * 2 + 0][0] = r0; bfl[half * 2 + 1][0] = r1;
                bfl[half * 2 + 0][1] = r2; bfl[half * 2 + 1][1] = r3;
            }
#pragma unroll
            for (int mt = 0; mt < 4; mt++)
#pragma unroll
                for (int nt = 0; nt < 4; nt++) {
                    mma16816(acc[mt][nt], afh[mt][0], afh[mt][1], afh[mt][2], afh[mt][3],
                             bfh[nt][0], bfh[nt][1]);
                    mma16816(acc[mt][nt], afh[mt][0], afh[mt][1], afh[mt][2], afh[mt][3],
                             bfl[nt][0], bfl[nt][1]);
                    mma16816(acc[mt][nt], afl[mt][0], afl[mt][1], afl[mt][2], afl[mt][3],
                             bfh[nt][0], bfh[nt][1]);
                }
        }
        __syncthreads();
        st ^= 1;
    }

    // ---- epilogue ----
#pragma unroll
    for (int mt = 0; mt < 4; mt++) {
        int row0 = bm + wm + mt * 16 + (lane >> 2);
#pragma unroll
        for (int nt = 0; nt < 4; nt++) {
            int col = bn + wn + nt * 8 + (lane & 3) * 2;
            if (col < N) {
                float b0 = bias ? bias[col] : 0.f;
                float b1 = bias ? bias[col + 1] : 0.f;
                float2 v0 = make_float2(acc[mt][nt][0] + b0, acc[mt][nt][1] + b1);
                float2 v1 = make_float2(acc[mt][nt][2] + b0, acc[mt][nt][3] + b1);
                *reinterpret_cast<float2*>(&C[(size_t)row0 * N + col]) = v0;
                *reinterpret_cast<float2*>(&C[(size_t)(row0 + 8) * N + col]) = v1;
            }
        }
    }
}

// ---------------- split conversions ----------------
__global__ void k_split(const float* __restrict__ x, __nv_bfloat16* __restrict__ hi,
                        __nv_bfloat16* __restrict__ lo, int n)
{
    int i = blockIdx.x * blockDim.x + threadIdx.x;
    if (i < n) { __nv_bfloat16 h, l; split_bf16(x[i], h, l); hi[i] = h; lo[i] = l; }
}
// W[K][N] fp32 -> out[N][K] bf16 hi/lo (K,N multiples of 32)
__global__ void k_splitT(const float* __restrict__ W, __nv_bfloat16* __restrict__ hiT,
                         __nv_bfloat16* __restrict__ loT, int K, int N)
{
    __shared__ float tile[32][33];
    int k0 = blockIdx.y * 32, n0 = blockIdx.x * 32;
    int tx = threadIdx.x, ty = threadIdx.y;
    for (int i = ty; i < 32; i += 8)
        tile[i][tx] = W[(size_t)(k0 + i) * N + n0 + tx];
    __syncthreads();
    for (int i = ty; i < 32; i += 8) {
        float v = tile[tx][i];
        __nv_bfloat16 h, l; split_bf16(v, h, l);
        size_t o = (size_t)(n0 + i) * K + k0 + tx;
        hiT[o] = h; loT[o] = l;
    }
}

// ---------------- embedding gather + split ----------------
__global__ void k_gather_x0(const int* __restrict__ ids, const float* __restrict__ emb,
                            __nv_bfloat16* __restrict__ x0h, __nv_bfloat16* __restrict__ x0l)
{
    int i = blockIdx.x, t = threadIdx.x;
    int id = ids[i];
    float v = (id == 0) ? 0.f : emb[(size_t)id * Hd + t];
    __nv_bfloat16 h, l; split_bf16(v, h, l);
    x0h[(size_t)i * Hd + t] = h;
    x0l[(size_t)i * Hd + t] = l;
}

// ---------------- attention logits ----------------
__global__ void k_alpha1(const float* __restrict__ h1, const float* __restrict__ attS,
                         const float* __restrict__ attD,
                         float* __restrict__ outS, float* __restrict__ outD)
{
    int i = blockIdx.x;
    int w = threadIdx.x >> 5, lane = threadIdx.x & 31;
    const float* hp = h1 + (size_t)i * F1 + w * Hd;
    const float* ap = attS + w * Hd;
    const float* dp = attD + w * Hd;
    float ss = 0.f, sd = 0.f;
#pragma unroll
    for (int u = 0; u < 8; u++) {
        float v = hp[lane + 32 * u];
        ss += v * ap[lane + 32 * u];
        sd += v * dp[lane + 32 * u];
    }
#pragma unroll
    for (int o = 16; o; o >>= 1) {
        ss += __shfl_xor_sync(0xffffffffu, ss, o);
        sd += __shfl_xor_sync(0xffffffffu, sd, o);
    }
    if (lane == 0) { outS[i * NHEADS + w] = ss; outD[i * NHEADS + w] = sd; }
}

__global__ void k_alpha2(const float* __restrict__ h2, const float* __restrict__ attS,
                         const float* __restrict__ attD,
                         float* __restrict__ outS, float* __restrict__ outD)
{
    __shared__ float shS[8], shD[8];
    int i = blockIdx.x, t = threadIdx.x;
    float v = h2[(size_t)i * Hd + t];
    float ss = v * attS[t], sd = v * attD[t];
    int lane = t & 31, w = t >> 5;
#pragma unroll
    for (int o = 16; o; o >>= 1) {
        ss += __shfl_xor_sync(0xffffffffu, ss, o);
        sd += __shfl_xor_sync(0xffffffffu, sd, o);
    }
    if (lane == 0) { shS[w] = ss; shD[w] = sd; }
    __syncthreads();
    if (t == 0) {
        float a = 0.f, b = 0.f;
#pragma unroll
        for (int u = 0; u < 8; u++) { a += shS[u]; b += shD[u]; }
        outS[i] = a; outD[i] = b;
    }
}

// ---------------- CSR build ----------------
__global__ void k_init_counts(int* __restrict__ counts)
{
    int i = blockIdx.x * blockDim.x + threadIdx.x;
    if (i < Nn) counts[i] = 1;
}
__global__ void k_count_edges(const int* __restrict__ ei, int* __restrict__ counts)
{
    int e = blockIdx.x * blockDim.x + threadIdx.x;
    if (e < Ee) atomicAdd(&counts[ei[Ee + e]], 1);
}
__global__ void k_scan16k(const int* __restrict__ counts, int* __restrict__ rowptr)
{
    __shared__ int wsum[32];
    const int tid = threadIdx.x;
    const int per = Nn / 1024;
    const int base = tid * per;
    int c[16];
    int tot = 0;
#pragma unroll
    for (int u = 0; u < per; u++) { c[u] = counts[base + u]; tot += c[u]; }
    int lane = tid & 31, wid = tid >> 5;
    int v = tot;
#pragma unroll
    for (int o = 1; o < 32; o <<= 1) {
        int t2 = __shfl_up_sync(0xffffffffu, v, o);
        if (lane >= o) v += t2;
    }
    if (lane == 31) wsum[wid] = v;
    __syncthreads();
    if (wid == 0) {
        int w = wsum[lane];
#pragma unroll
        for (int o = 1; o < 32; o <<= 1) {
            int t2 = __shfl_up_sync(0xffffffffu, w, o);
            if (lane >= o) w += t2;
        }
        wsum[lane] = w;
    }
    __syncthreads();
    int run = (v - tot) + (wid > 0 ? wsum[wid - 1] : 0);
#pragma unroll
    for (int u = 0; u < per; u++) { rowptr[base + u] = run; run += c[u]; }
    if (tid == 1023) rowptr[Nn] = run;
}
__global__ void k_copy_cursor(const int* __restrict__ rowptr, int* __restrict__ cursor)
{
    int i = blockIdx.x * blockDim.x + threadIdx.x;
    if (i < Nn) cursor[i] = rowptr[i];
}
__global__ void k_scatter_edges(const int* __restrict__ ei,
                                int* __restrict__ cursor, int* __restrict__ colsrc)
{
    int e = blockIdx.x * blockDim.x + threadIdx.x;
    if (e < Ee) {
        int d = ei[Ee + e];
        int p = atomicAdd(&cursor[d], 1);
        colsrc[p] = ei[e];
    }
}
__global__ void k_scatter_loops(int* __restrict__ cursor, int* __restrict__ colsrc)
{
    int i = blockIdx.x * blockDim.x + threadIdx.x;
    if (i < Nn) {
        int p = atomicAdd(&cursor[i], 1);
        colsrc[p] = i;
    }
}

// ---------------- GAT aggregation (fused bf16 split on output) ----------------
__global__ void k_gat1_agg(const float* __restrict__ h1,
                           const float* __restrict__ aS, const float* __restrict__ aD,
                           const int* __restrict__ rowptr, const int* __restrict__ colsrc,
                           const float* __restrict__ b1,
                           __nv_bfloat16* __restrict__ x1h, __nv_bfloat16* __restrict__ x1l)
{
    int dst = blockIdx.x;
    int w = threadIdx.x >> 5, lane = threadIdx.x & 31;
    int beg = rowptr[dst], end = rowptr[dst + 1];
    float adv = aD[dst * NHEADS + w];

    float m = -3.4e38f;
    for (int e = beg; e < end; e++) {
        float v = aS[colsrc[e] * NHEADS + w] + adv;
        v = v > 0.f ? v : 0.2f * v;
        m = fmaxf(m, v);
    }
    float acc[8] = {0.f, 0.f, 0.f, 0.f, 0.f, 0.f, 0.f, 0.f};
    float sump = 0.f;
    for (int e = beg; e < end; e++) {
        int s = colsrc[e];
        float v = aS[s * NHEADS + w] + adv;
        v = v > 0.f ? v : 0.2f * v;
        float p = expf(v - m);
        sump += p;
        const float* hp = h1 + (size_t)s * F1 + w * Hd + lane;
#pragma unroll
        for (int u = 0; u < 8; u++) acc[u] += p * hp[u * 32];
    }
    float inv = 1.f / (sump + 1e-16f);
    size_t base = (size_t)dst * F1 + w * Hd + lane;
    const float* bp = b1 + w * Hd + lane;
#pragma unroll
    for (int u = 0; u < 8; u++) {
        float o = acc[u] * inv + bp[u * 32];
        o = o > 0.f ? o : expm1f(o);           // ELU
        __nv_bfloat16 h, l; split_bf16(o, h, l);
        x1h[base + u * 32] = h;
        x1l[base + u * 32] = l;
    }
}

__global__ void k_gat2_agg(const float* __restrict__ h2,
                           const float* __restrict__ aS, const float* __restrict__ aD,
                           const int* __restrict__ rowptr, const int* __restrict__ colsrc,
                           const float* __restrict__ b2,
                           __nv_bfloat16* __restrict__ o2h, __nv_bfloat16* __restrict__ o2l)
{
    int dst = blockIdx.x, t = threadIdx.x;
    int beg = rowptr[dst], end = rowptr[dst + 1];
    float adv = aD[dst];
    float m = -3.4e38f;
    for (int e = beg; e < end; e++) {
        float v = aS[colsrc[e]] + adv;
        v = v > 0.f ? v : 0.2f * v;
        m = fmaxf(m, v);
    }
    float acc = 0.f, sump = 0.f;
    for (int e = beg; e < end; e++) {
        int s = colsrc[e];
        float v = aS[s] + adv;
        v = v > 0.f ? v : 0.2f * v;
        float p = expf(v - m);
        sump += p;
        acc += p * h2[(size_t)s * Hd + t];
    }
    float o = acc / (sump + 1e-16f) + b2[t];
    __nv_bfloat16 h, l; split_bf16(o, h, l);
    o2h[(size_t)dst * Hd + t] = h;
    o2l[(size_t)dst * Hd + t] = l;
}

// ---------------- sequence bookkeeping ----------------
__global__ void k_zero_len(int* __restrict__ len) { len[threadIdx.x] = 0; }
__global__ void k_count_len(const int* __restrict__ batch, int* __restrict__ len)
{
    int i = blockIdx.x * blockDim.x + threadIdx.x;
    if (i < Nn) atomicAdd(&len[batch[i]], 1);
}
__global__ void k_scan256(const int* __restrict__ len, int* __restrict__ starts)
{
    __shared__ int wsum[8];
    int tid = threadIdx.x;
    int orig = len[tid];
    int v = orig;
    int lane = tid & 31, wid = tid >> 5;
#pragma unroll
    for (int o = 1; o < 32; o <<= 1) {
        int t2 = __shfl_up_sync(0xffffffffu, v, o);
        if (lane >= o) v += t2;
    }
    if (lane == 31) wsum[wid] = v;
    __syncthreads();
    if (tid == 0) {
        int s = 0;
#pragma unroll
        for (int u = 0; u < 8; u++) { int t2 = wsum[u]; wsum[u] = s; s += t2; }
    }
    __syncthreads();
    starts[tid] = (v - orig) + wsum[wid];
}
__global__ void k_nodeidx(const int* __restrict__ batch, const int* __restrict__ starts,
                          int* __restrict__ nodeidx)
{
    int i = blockIdx.x * blockDim.x + threadIdx.x;
    if (i < Nn) {
        int b = batch[i];
        int p = i - starts[b];
        if (p >= 0 && p < Lseq) nodeidx[b * Lseq + p] = i;
    }
}
__global__ void k_bsum(const float* __restrict__ bih, const float* __restrict__ bhh,
                       float* __restrict__ bs)
{
    int k = blockIdx.x * blockDim.x + threadIdx.x;
    if (k < G4) bs[k] = bih[k] + bhh[k];
}
__global__ void k_zero_h(float* __restrict__ h)
{
    int i = blockIdx.x * blockDim.x + threadIdx.x;
    h[i] = 0.f;
}

// ---------------- persistent fused LSTM ----------------
#define WST 68
__global__ void __launch_bounds__(256, 1)
k_lstm(const float* __restrict__ xg, const int* __restrict__ nodeidx,
       const int* __restrict__ len, float* __restrict__ hbuf0,
       float* __restrict__ hbuf1, const float* __restrict__ Whh)
{
    extern __shared__ float sm[];
    float* WshT = sm;
    float* HshT = sm + 256 * WST;
    float* red  = HshT + 256 * 33;
    float* csh  = red + 4 * 64 * 33;

    const int tid  = threadIdx.x;
    const int jb   = blockIdx.x & 15;
    const int mb   = blockIdx.x >> 4;
    const int kg   = tid >> 6;
    const int t64  = tid & 63;
    const int rowq = t64 & 15;
    const int bq   = t64 >> 4;

    unsigned my_gen = atomicAdd(&g_bar_gen, 0u);

    for (int idx = tid; idx < 64 * 256; idx += 256) {
        int r = idx >> 8;
        int k = idx & 255;
        int g = r >> 4, u = r & 15;
        WshT[k * WST + r] = Whh[(size_t)(g * 256 + jb * 16 + u) * 256 + k];
    }
    if (tid < 256) { csh[tid & 511] = 0.f; if (tid + 256 < 512) csh[tid + 256] = 0.f; }

    for (int t = 0; t < Lseq; t++) {
        const float* hc = (t & 1) ? hbuf1 : hbuf0;
#pragma unroll
        for (int l = 0; l < 32; l++) {
            int idx = tid + l * 256;
            int bl = idx >> 8, k = idx & 255;
            HshT[k * 33 + bl] = __ldcg(&hc[(mb * 32 + bl) * 256 + k]);
        }
        __syncthreads();

        float acc[4][8];
#pragma unroll
        for (int i = 0; i < 4; i++)
#pragma unroll
            for (int j = 0; j < 8; j++) acc[i][j] = 0.f;
        const int k0 = kg * 64;
#pragma unroll 4
        for (int k = k0; k < k0 + 64; k++) {
            float4 w = *reinterpret_cast<const float4*>(&WshT[k * WST + rowq * 4]);
            const float* hr = &HshT[k * 33 + bq * 8];
#pragma unroll
            for (int j = 0; j < 8; j++) {
                float hv = hr[j];
                acc[0][j] += w.x * hv;
                acc[1][j] += w.y * hv;
                acc[2][j] += w.z * hv;
                acc[3][j] += w.w * hv;
            }
        }
#pragma unroll
        for (int i = 0; i < 4; i++)
#pragma unroll
            for (int j = 0; j < 8; j++)
                red[kg * (64 * 33) + (rowq * 4 + i) * 33 + bq * 8 + j] = acc[i][j];
        __syncthreads();

        float* hn_buf = (t & 1) ? hbuf0 : hbuf1;
#pragma unroll
        for (int p = tid; p < 512; p += 256) {
            int u = p & 15;
            int bl = p >> 4;
            int bglob = mb * 32 + bl;
            int node = nodeidx[bglob * Lseq + t];
            const float* xp = xg + (size_t)node * G4 + jb * 16 + u;
            float gi = 0.f, gf = 0.f, gg = 0.f, go = 0.f;
#pragma unroll
            for (int q = 0; q < 4; q++) {
                const float* rq = red + q * (64 * 33);
                gi += rq[(0 * 16 + u) * 33 + bl];
                gf += rq[(1 * 16 + u) * 33 + bl];
                gg += rq[(2 * 16 + u) * 33 + bl];
                go += rq[(3 * 16 + u) * 33 + bl];
            }
            gi += xp[0]; gf += xp[256]; gg += xp[512]; go += xp[768];
            float hprev = HshT[(jb * 16 + u) * 33 + bl];
            float cprev = csh[u * 32 + bl];
            float si = 1.f / (1.f + expf(-gi));
            float sf = 1.f / (1.f + expf(-gf));
            float so = 1.f / (1.f + expf(-go));
            float cn = sf * cprev + si * tanhf(gg);
            float hn = so * tanhf(cn);
            bool act = (t < len[bglob]);
            if (act) csh[u * 32 + bl] = cn;
            float hw = act ? hn : hprev;
            __stcg(&hn_buf[bglob * 256 + jb * 16 + u], hw);
        }

        if (t != Lseq - 1) {
            __threadfence();
            __syncthreads();
            if (tid == 0) {
                unsigned old = atomicAdd(&g_bar_arrive, 1u);
                if (old == LSTM_BLOCKS - 1) {
                    atomicExch(&g_bar_arrive, 0u);
                    __threadfence();
                    atomicAdd(&g_bar_gen, 1u);
                } else {
                    while (atomicAdd(&g_bar_gen, 0u) == my_gen) __nanosleep(64);
                }
            }
            __syncthreads();
            my_gen++;
        }
    }
}

// ---------------- host launcher ----------------
extern "C" void kernel_launch(void* const* d_in, const int* in_sizes, int n_in,
                              void* d_out, int out_size)
{
    const int*   x_ids = (const int*)d_in[0];
    const int*   ei    = (const int*)d_in[1];
    const int*   batch = (const int*)d_in[2];
    const float* emb   = (const float*)d_in[3];
    const float* W1    = (const float*)d_in[4];
    const float* attS1 = (const float*)d_in[5];
    const float* attD1 = (const float*)d_in[6];
    const float* b1    = (const float*)d_in[7];
    const float* W2    = (const float*)d_in[8];
    const float* attS2 = (const float*)d_in[9];
    const float* attD2 = (const float*)d_in[10];
    const float* b2    = (const float*)d_in[11];
    const float* Wih   = (const float*)d_in[12];
    const float* Whh   = (const float*)d_in[13];
    const float* bih   = (const float*)d_in[14];
    const float* bhh   = (const float*)d_in[15];
    const float* Wp    = (const float*)d_in[16];
    const float* bp    = (const float*)d_in[17];
    float* out = (float*)d_out;

    void* p;
    cudaGetSymbolAddress(&p, g_h1);      float* h1   = (float*)p;
    cudaGetSymbolAddress(&p, g_h2);      float* h2   = (float*)p;
    cudaGetSymbolAddress(&p, g_xg);      float* xg   = (float*)p;
    cudaGetSymbolAddress(&p, g_as1);     float* as1  = (float*)p;
    cudaGetSymbolAddress(&p, g_ad1);     float* ad1  = (float*)p;
    cudaGetSymbolAddress(&p, g_as2);     float* as2  = (float*)p;
    cudaGetSymbolAddress(&p, g_ad2);     float* ad2  = (float*)p;
    cudaGetSymbolAddress(&p, g_counts);  int* counts = (int*)p;
    cudaGetSymbolAddress(&p, g_rowptr);  int* rowptr = (int*)p;
    cudaGetSymbolAddress(&p, g_cursor);  int* cursor = (int*)p;
    cudaGetSymbolAddress(&p, g_colsrc);  int* colsrc = (int*)p;
    cudaGetSymbolAddress(&p, g_len);     int* len    = (int*)p;
    cudaGetSymbolAddress(&p, g_starts);  int* starts = (int*)p;
    cudaGetSymbolAddress(&p, g_nodeidx); int* nodeidx= (int*)p;
    cudaGetSymbolAddress(&p, g_hbuf1);   float* hb1  = (float*)p;
    cudaGetSymbolAddress(&p, g_h);       float* hS   = (float*)p;
    cudaGetSymbolAddress(&p, g_bsum);    float* bsum = (float*)p;

    __nv_bfloat16 *x0h, *x0l, *x1h, *x1l, *o2h, *o2l;
    __nv_bfloat16 *W1Th, *W1Tl, *W2Th, *W2Tl, *Wihh, *Wihl, *hTh, *hTl, *Wph, *Wpl;
    cudaGetSymbolAddress(&p, g_x0h); x0h = (__nv_bfloat16*)p;
    cudaGetSymbolAddress(&p, g_x0l); x0l = (__nv_bfloat16*)p;
    cudaGetSymbolAddress(&p, g_x1h); x1h = (__nv_bfloat16*)p;
    cudaGetSymbolAddress(&p, g_x1l); x1l = (__nv_bfloat16*)p;
    cudaGetSymbolAddress(&p, g_o2h); o2h = (__nv_bfloat16*)p;
    cudaGetSymbolAddress(&p, g_o2l); o2l = (__nv_bfloat16*)p;
    cudaGetSymbolAddress(&p, g_W1Th); W1Th = (__nv_bfloat16*)p;
    cudaGetSymbolAddress(&p, g_W1Tl); W1Tl = (__nv_bfloat16*)p;
    cudaGetSymbolAddress(&p, g_W2Th); W2Th = (__nv_bfloat16*)p;
    cudaGetSymbolAddress(&p, g_W2Tl); W2Tl = (__nv_bfloat16*)p;
    cudaGetSymbolAddress(&p, g_Wihh); Wihh = (__nv_bfloat16*)p;
    cudaGetSymbolAddress(&p, g_Wihl); Wihl = (__nv_bfloat16*)p;
    cudaGetSymbolAddress(&p, g_hTh);  hTh  = (__nv_bfloat16*)p;
    cudaGetSymbolAddress(&p, g_hTl);  hTl  = (__nv_bfloat16*)p;
    cudaGetSymbolAddress(&p, g_Wph);  Wph  = (__nv_bfloat16*)p;
    cudaGetSymbolAddress(&p, g_Wpl);  Wpl  = (__nv_bfloat16*)p;

    static const int LSTM_SMEM = (256 * WST + 256 * 33 + 4 * 64 * 33 + 512) * 4;
    cudaFuncSetAttribute(k_lstm, cudaFuncAttributeMaxDynamicSharedMemorySize, LSTM_SMEM);
    cudaFuncSetAttribute(k_gemm_bf3, cudaFuncAttributeMaxDynamicSharedMemorySize, GEMM_SMEM);

    // 1) embedding gather with fused bf16 split
    k_gather_x0<<<Nn, Hd>>>(x_ids, emb, x0h, x0l);

    // weight conversions (constant work, small)
    k_splitT<<<dim3(F1 / 32, Hd / 32), dim3(32, 8)>>>(W1, W1Th, W1Tl, Hd, F1);
    k_splitT<<<dim3(Hd / 32, F1 / 32), dim3(32, 8)>>>(W2, W2Th, W2Tl, F1, Hd);
    k_split<<<(G4 * Hd + 255) / 256, 256>>>(Wih, Wihh, Wihl, G4 * Hd);
    k_split<<<(NNODE_ * Hd + 255) / 256, 256>>>(Wp, Wph, Wpl, NNODE_ * Hd);

    // 2) h1 = x0 @ W1  (tensor cores, bf16x3)
    k_gemm_bf3<<<dim3(F1 / GBN, Nn / GBM), 256, GEMM_SMEM>>>(
        x0h, x0l, W1Th, W1Tl, h1, Nn, F1, Hd, nullptr);

    // 3) attention logits (layer 1)
    k_alpha1<<<Nn, 256>>>(h1, attS1, attD1, as1, ad1);

    // 4) CSR by dst
    k_init_counts<<<Nn / 256, 256>>>(counts);
    k_count_edges<<<Ee / 256, 256>>>(ei, counts);
    k_scan16k<<<1, 1024>>>(counts, rowptr);
    k_copy_cursor<<<Nn / 256, 256>>>(rowptr, cursor);
    k_scatter_edges<<<Ee / 256, 256>>>(ei, cursor, colsrc);
    k_scatter_loops<<<Nn / 256, 256>>>(cursor, colsrc);

    // 5) GAT1 aggregate + b1 + ELU -> x1 (bf16 split fused)
    k_gat1_agg<<<Nn, 256>>>(h1, as1, ad1, rowptr, colsrc, b1, x1h, x1l);

    // 6) h2 = x1 @ W2
    k_gemm_bf3<<<dim3(Hd / GBN, Nn / GBM), 256, GEMM_SMEM>>>(
        x1h, x1l, W2Th, W2Tl, h2, Nn, Hd, F1, nullptr);

    // 7) layer-2 logits
    k_alpha2<<<Nn, 256>>>(h2, attS2, attD2, as2, ad2);

    // 8) GAT2 aggregate + b2 -> out2 (bf16 split fused)
    k_gat2_agg<<<Nn, 256>>>(h2, as2, ad2, rowptr, colsrc, b2, o2h, o2l);

    // 9) sequence bookkeeping
    k_zero_len<<<1, Bsz>>>(len);
    k_count_len<<<Nn / 256, 256>>>(batch, len);
    k_scan256<<<1, Bsz>>>(len, starts);
    k_nodeidx<<<Nn / 256, 256>>>(batch, starts, nodeidx);
    k_bsum<<<G4 / 256, 256>>>(bih, bhh, bsum);

    // 10) xg = out2 @ Wih^T + (bih + bhh)
    k_gemm_bf3<<<dim3(G4 / GBN, Nn / GBM), 256, GEMM_SMEM>>>(
        o2h, o2l, Wihh, Wihl, xg, Nn, G4, Hd, bsum);

    // 11) persistent fused LSTM
    k_zero_h<<<(Bsz * Hd) / 256, 256>>>(hS);
    k_lstm<<<LSTM_BLOCKS, 256, LSTM_SMEM>>>(xg, nodeidx, len, hS, hb1, Whh);

    // 12) out = hT @ Wp^T + bp
    k_split<<<(Bsz * Hd + 255) / 256, 256>>>(hS, hTh, hTl, Bsz * Hd);
    k_gemm_bf3<<<dim3((NNODE_ + GBN - 1) / GBN, Bsz / GBM), 256, GEMM_SMEM>>>(
        hTh, hTl, Wph, Wpl, out, Bsz, NNODE_, Hd, bp);
}

// round 8
// speedup vs baseline: 1.7585x; 1.0120x over previous
#include <cuda_runtime.h>
#include <cuda_bf16.h>
#include <stdint.h>
#include <math.h>

typedef unsigned int u32;

// ---------------- problem constants ----------------
#define Nn      16384
#define Ee      131072
#define ETOT    (Ee + Nn)
#define Bsz     256
#define Lseq    64
#define Hd      256
#define NHEADS  8
#define F1      2048
#define G4      1024
#define NNODE_  37000

#define LSTM_BLOCKS 128

// ---------------- device scratch ----------------
__device__ float g_h1  [(size_t)Nn * F1];
__device__ float g_h2  [(size_t)Nn * Hd];
__device__ float g_xg  [(size_t)Nn * G4];
__device__ float g_as1 [Nn * NHEADS];
__device__ float g_ad1 [Nn * NHEADS];
__device__ float g_as2 [Nn];
__device__ float g_ad2 [Nn];
__device__ int   g_counts[Nn];
__device__ int   g_rowptr[Nn + 1];
__device__ int   g_cursor[Nn];
__device__ int   g_colsrc[ETOT];
__device__ int   g_len   [Bsz];
__device__ int   g_starts[Bsz];
__device__ int   g_nodeidx[Bsz * Lseq];
__device__ float g_hbuf1[Bsz * Hd];
__device__ float g_h    [Bsz * Hd];
__device__ float g_bsum [G4];
__device__ unsigned g_bar_arrive = 0;
__device__ unsigned g_bar_gen    = 0;

// bf16 hi/lo split operands for tensor-core GEMMs
__device__ __nv_bfloat16 g_x0h[(size_t)Nn * Hd],  g_x0l[(size_t)Nn * Hd];
__device__ __nv_bfloat16 g_x1h[(size_t)Nn * F1],  g_x1l[(size_t)Nn * F1];
__device__ __nv_bfloat16 g_o2h[(size_t)Nn * Hd],  g_o2l[(size_t)Nn * Hd];
__device__ __nv_bfloat16 g_W1Th[(size_t)F1 * Hd], g_W1Tl[(size_t)F1 * Hd];
__device__ __nv_bfloat16 g_W2Th[(size_t)Hd * F1], g_W2Tl[(size_t)Hd * F1];
__device__ __nv_bfloat16 g_Wihh[(size_t)G4 * Hd], g_Wihl[(size_t)G4 * Hd];
__device__ __nv_bfloat16 g_hTh[Bsz * Hd],         g_hTl[Bsz * Hd];
__device__ __nv_bfloat16 g_Wph[(size_t)NNODE_ * Hd], g_Wpl[(size_t)NNODE_ * Hd];

// ---------------- small helpers ----------------
__device__ __forceinline__ void split_bf16(float v, __nv_bfloat16& h, __nv_bfloat16& l)
{
    h = __float2bfloat16(v);
    l = __float2bfloat16(v - __bfloat162float(h));
}
__device__ __forceinline__ u32 smem_u32(const void* p)
{
    return (u32)__cvta_generic_to_shared(p);
}
__device__ __forceinline__ void cp16(u32 dst, const void* src, int srcsize)
{
    asm volatile("cp.async.cg.shared.global [%0], [%1], 16, %2;"
                 :: "r"(dst), "l"(src), "r"(srcsize) : "memory");
}
__device__ __forceinline__ void cp_commit()
{
    asm volatile("cp.async.commit_group;" ::: "memory");
}
template<int NG>
__device__ __forceinline__ void cp_wait()
{
    asm volatile("cp.async.wait_group %0;" :: "n"(NG) : "memory");
}
__device__ __forceinline__ void ldsm_x4(u32 a, u32& r0, u32& r1, u32& r2, u32& r3)
{
    asm volatile("ldmatrix.sync.aligned.m8n8.x4.shared.b16 {%0,%1,%2,%3},[%4];"
                 : "=r"(r0), "=r"(r1), "=r"(r2), "=r"(r3) : "r"(a));
}
__device__ __forceinline__ void mma16816(float* c, u32 a0, u32 a1, u32 a2, u32 a3,
                                         u32 b0, u32 b1)
{
    asm volatile("mma.sync.aligned.m16n8k16.row.col.f32.bf16.bf16.f32 "
                 "{%0,%1,%2,%3},{%4,%5,%6,%7},{%8,%9},{%0,%1,%2,%3};"
                 : "+f"(c[0]), "+f"(c[1]), "+f"(c[2]), "+f"(c[3])
                 : "r"(a0), "r"(a1), "r"(a2), "r"(a3), "r"(b0), "r"(b1));
}

// ---------------- bf16x3 tensor-core GEMM ----------------
// C[M,N] = (Ah+Al)[M,K] @ (Bh+Bl)[N,K]^T + bias   (3-term product, fp32 acc)
// M % 128 == 0, K % 32 == 0 (N guarded per row).
// 2 CTAs/SM (160KB smem total) for 4 warps/SMSP latency hiding.
#define GBM 128
#define GBN 128
#define GBK 32
#define BROW 40                       // smem row stride (bf16 elems)
#define ABUF (GBM * BROW)             // elems per (stage,hl) buffer
#define GEMM_SMEM (8 * ABUF * 2)      // bytes: As[2][2] + Bs[2][2]

__global__ void __launch_bounds__(256, 2)
k_gemm_bf3(const __nv_bfloat16* __restrict__ Ah, const __nv_bfloat16* __restrict__ Al,
           const __nv_bfloat16* __restrict__ Bh, const __nv_bfloat16* __restrict__ Bl,
           float* __restrict__ C, int M, int N, int K, const float* __restrict__ bias)
{
    extern __shared__ __nv_bfloat16 smg[];
    __nv_bfloat16* As = smg;              // [st][hl][128*BROW]
    __nv_bfloat16* Bs = smg + 4 * ABUF;
    const u32 sA = smem_u32(As);
    const u32 sB = smem_u32(Bs);

    const int tid  = threadIdx.x;
    const int bm   = blockIdx.y * GBM;
    const int bn   = blockIdx.x * GBN;
    const int warp = tid >> 5, lane = tid & 31;
    const int wm   = (warp >> 2) * 64;    // 2 warps along m
    const int wn   = (warp & 3) * 32;     // 4 warps along n

    float acc[4][4][4];
#pragma unroll
    for (int i = 0; i < 4; i++)
#pragma unroll
        for (int j = 0; j < 4; j++)
#pragma unroll
            for (int u = 0; u < 4; u++) acc[i][j][u] = 0.f;

    const int nstage = K / GBK;

    // ---- async stage loader: 2 chunks/thread per matrix ----
    auto loadstage = [&](int kt, int st) {
        const int k0 = kt * GBK;
#pragma unroll
        for (int l = 0; l < 2; l++) {
            int i = tid + l * 256;
            int r = i >> 2, s = (i & 3) * 8;
            u32 doffA = (u32)((r * BROW + s) * 2);
            size_t ga = (size_t)(bm + r) * K + k0 + s;
            cp16(sA + (u32)(st * 2 + 0) * (ABUF * 2) + doffA, Ah + ga, 16);
            cp16(sA + (u32)(st * 2 + 1) * (ABUF * 2) + doffA, Al + ga, 16);
            int nrow = bn + r;
            int ok = (nrow < N) ? 16 : 0;
            int nc = (nrow < N) ? nrow : (N - 1);
            size_t gb = (size_t)nc * K + k0 + s;
            cp16(sB + (u32)(st * 2 + 0) * (ABUF * 2) + doffA, Bh + gb, ok);
            cp16(sB + (u32)(st * 2 + 1) * (ABUF * 2) + doffA, Bl + gb, ok);
        }
        cp_commit();
    };

    loadstage(0, 0);
    int st = 0;
    for (int kt = 0; kt < nstage; kt++) {
        if (kt + 1 < nstage) { loadstage(kt + 1, st ^ 1); cp_wait<1>(); }
        else                 { cp_wait<0>(); }
        __syncthreads();

#pragma unroll
        for (int kk = 0; kk < 2; kk++) {
            u32 afh[4][4], afl[4][4];
#pragma unroll
            for (int mt = 0; mt < 4; mt++) {
                u32 off = (u32)(((wm + mt * 16 + (lane & 15)) * BROW
                          + kk * 16 + (lane >> 4) * 8) * 2);
                ldsm_x4(sA + (u32)(st * 2 + 0) * (ABUF * 2) + off,
                        afh[mt][0], afh[mt][1], afh[mt][2], afh[mt][3]);
                ldsm_x4(sA + (u32)(st * 2 + 1) * (ABUF * 2) + off,
                        afl[mt][0], afl[mt][1], afl[mt][2], afl[mt][3]);
            }
            u32 bfh[4][2], bfl[4][2];
#pragma unroll
            for (int half = 0; half < 2; half++) {
                int g = lane >> 3;
                u32 off = (u32)(((wn + half * 16 + (g & 1) * 8 + (lane & 7)) * BROW
                          + kk * 16 + (g >> 1) * 8) * 2);
                u32 r0, r1, r2, r3;
                ldsm_x4(sB + (u32)(st * 2 + 0) * (ABUF * 2) + off, r0, r1, r2, r3);
                bfh[half * 2 + 0][0] = r0; bfh[half * 2 + 1][0] = r1;
                bfh[half * 2 + 0][1] = r2; bfh[half * 2 + 1][1] = r3;
                ldsm_x4(sB + (u32)(st * 2 + 1) * (ABUF * 2) + off, r0, r1, r2, r3);
                bfl[half * 2 + 0][0] = r0; bfl[half * 2 + 1][0] = r1;
                bfl[half * 2 + 0][1] = r2; bfl[half * 2 + 1][1] = r3;
            }
#pragma unroll
            for (int mt = 0; mt < 4; mt++)
#pragma unroll
                for (int nt = 0; nt < 4; nt++) {
                    mma16816(acc[mt][nt], afh[mt][0], afh[mt][1], afh[mt][2], afh[mt][3],
                             bfh[nt][0], bfh[nt][1]);
                    mma16816(acc[mt][nt], afh[mt][0], afh[mt][1], afh[mt][2], afh[mt][3],
                             bfl[nt][0], bfl[nt][1]);
                    mma16816(acc[mt][nt], afl[mt][0], afl[mt][1], afl[mt][2], afl[mt][3],
                             bfh[nt][0], bfh[nt][1]);
                }
        }
        __syncthreads();
        st ^= 1;
    }

    // ---- epilogue ----
#pragma unroll
    for (int mt = 0; mt < 4; mt++) {
        int row0 = bm + wm + mt * 16 + (lane >> 2);
#pragma unroll
        for (int nt = 0; nt < 4; nt++) {
            int col = bn + wn + nt * 8 + (lane & 3) * 2;
            if (col < N) {
                float b0 = bias ? bias[col] : 0.f;
                float b1 = bias ? bias[col + 1] : 0.f;
                float2 v0 = make_float2(acc[mt][nt][0] + b0, acc[mt][nt][1] + b1);
                float2 v1 = make_float2(acc[mt][nt][2] + b0, acc[mt][nt][3] + b1);
                *reinterpret_cast<float2*>(&C[(size_t)row0 * N + col]) = v0;
                *reinterpret_cast<float2*>(&C[(size_t)(row0 + 8) * N + col]) = v1;
            }
        }
    }
}

// ---------------- split conversions ----------------
__global__ void k_split(const float* __restrict__ x, __nv_bfloat16* __restrict__ hi,
                        __nv_bfloat16* __restrict__ lo, int n)
{
    int i = blockIdx.x * blockDim.x + threadIdx.x;
    if (i < n) { __nv_bfloat16 h, l; split_bf16(x[i], h, l); hi[i] = h; lo[i] = l; }
}
// W[K][N] fp32 -> out[N][K] bf16 hi/lo (K,N multiples of 32)
__global__ void k_splitT(const float* __restrict__ W, __nv_bfloat16* __restrict__ hiT,
                         __nv_bfloat16* __restrict__ loT, int K, int N)
{
    __shared__ float tile[32][33];
    int k0 = blockIdx.y * 32, n0 = blockIdx.x * 32;
    int tx = threadIdx.x, ty = threadIdx.y;
    for (int i = ty; i < 32; i += 8)
        tile[i][tx] = W[(size_t)(k0 + i) * N + n0 + tx];
    __syncthreads();
    for (int i = ty; i < 32; i += 8) {
        float v = tile[tx][i];
        __nv_bfloat16 h, l; split_bf16(v, h, l);
        size_t o = (size_t)(n0 + i) * K + k0 + tx;
        hiT[o] = h; loT[o] = l;
    }
}

// ---------------- embedding gather + split ----------------
__global__ void k_gather_x0(const int* __restrict__ ids, const float* __restrict__ emb,
                            __nv_bfloat16* __restrict__ x0h, __nv_bfloat16* __restrict__ x0l)
{
    int i = blockIdx.x, t = threadIdx.x;
    int id = ids[i];
    float v = (id == 0) ? 0.f : emb[(size_t)id * Hd + t];
    __nv_bfloat16 h, l; split_bf16(v, h, l);
    x0h[(size_t)i * Hd + t] = h;
    x0l[(size_t)i * Hd + t] = l;
}

// ---------------- attention logits ----------------
__global__ void k_alpha1(const float* __restrict__ h1, const float* __restrict__ attS,
                         const float* __restrict__ attD,
                         float* __restrict__ outS, float* __restrict__ outD)
{
    int i = blockIdx.x;
    int w = threadIdx.x >> 5, lane = threadIdx.x & 31;
    const float* hp = h1 + (size_t)i * F1 + w * Hd;
    const float* ap = attS + w * Hd;
    const float* dp = attD + w * Hd;
    float ss = 0.f, sd = 0.f;
#pragma unroll
    for (int u = 0; u < 8; u++) {
        float v = hp[lane + 32 * u];
        ss += v * ap[lane + 32 * u];
        sd += v * dp[lane + 32 * u];
    }
#pragma unroll
    for (int o = 16; o; o >>= 1) {
        ss += __shfl_xor_sync(0xffffffffu, ss, o);
        sd += __shfl_xor_sync(0xffffffffu, sd, o);
    }
    if (lane == 0) { outS[i * NHEADS + w] = ss; outD[i * NHEADS + w] = sd; }
}

__global__ void k_alpha2(const float* __restrict__ h2, const float* __restrict__ attS,
                         const float* __restrict__ attD,
                         float* __restrict__ outS, float* __restrict__ outD)
{
    __shared__ float shS[8], shD[8];
    int i = blockIdx.x, t = threadIdx.x;
    float v = h2[(size_t)i * Hd + t];
    float ss = v * attS[t], sd = v * attD[t];
    int lane = t & 31, w = t >> 5;
#pragma unroll
    for (int o = 16; o; o >>= 1) {
        ss += __shfl_xor_sync(0xffffffffu, ss, o);
        sd += __shfl_xor_sync(0xffffffffu, sd, o);
    }
    if (lane == 0) { shS[w] = ss; shD[w] = sd; }
    __syncthreads();
    if (t == 0) {
        float a = 0.f, b = 0.f;
#pragma unroll
        for (int u = 0; u < 8; u++) { a += shS[u]; b += shD[u]; }
        outS[i] = a; outD[i] = b;
    }
}

// ---------------- CSR build ----------------
__global__ void k_init_counts(int* __restrict__ counts)
{
    int i = blockIdx.x * blockDim.x + threadIdx.x;
    if (i < Nn) counts[i] = 1;
}
__global__ void k_count_edges(const int* __restrict__ ei, int* __restrict__ counts)
{
    int e = blockIdx.x * blockDim.x + threadIdx.x;
    if (e < Ee) atomicAdd(&counts[ei[Ee + e]], 1);
}
// scan + write rowptr AND cursor (merged copy_cursor)
__global__ void k_scan16k(const int* __restrict__ counts, int* __restrict__ rowptr,
                          int* __restrict__ cursor)
{
    __shared__ int wsum[32];
    const int tid = threadIdx.x;
    const int per = Nn / 1024;
    const int base = tid * per;
    int c[16];
    int tot = 0;
#pragma unroll
    for (int u = 0; u < per; u++) { c[u] = counts[base + u]; tot += c[u]; }
    int lane = tid & 31, wid = tid >> 5;
    int v = tot;
#pragma unroll
    for (int o = 1; o < 32; o <<= 1) {
        int t2 = __shfl_up_sync(0xffffffffu, v, o);
        if (lane >= o) v += t2;
    }
    if (lane == 31) wsum[wid] = v;
    __syncthreads();
    if (wid == 0) {
        int w = wsum[lane];
#pragma unroll
        for (int o = 1; o < 32; o <<= 1) {
            int t2 = __shfl_up_sync(0xffffffffu, w, o);
            if (lane >= o) w += t2;
        }
        wsum[lane] = w;
    }
    __syncthreads();
    int run = (v - tot) + (wid > 0 ? wsum[wid - 1] : 0);
#pragma unroll
    for (int u = 0; u < per; u++) {
        rowptr[base + u] = run;
        cursor[base + u] = run;
        run += c[u];
    }
    if (tid == 1023) rowptr[Nn] = run;
}
__global__ void k_scatter_edges(const int* __restrict__ ei,
                                int* __restrict__ cursor, int* __restrict__ colsrc)
{
    int e = blockIdx.x * blockDim.x + threadIdx.x;
    if (e < Ee) {
        int d = ei[Ee + e];
        int p = atomicAdd(&cursor[d], 1);
        colsrc[p] = ei[e];
    }
}
__global__ void k_scatter_loops(int* __restrict__ cursor, int* __restrict__ colsrc)
{
    int i = blockIdx.x * blockDim.x + threadIdx.x;
    if (i < Nn) {
        int p = atomicAdd(&cursor[i], 1);
        colsrc[p] = i;
    }
}

// ---------------- GAT aggregation (fused bf16 split on output) ----------------
__global__ void k_gat1_agg(const float* __restrict__ h1,
                           const float* __restrict__ aS, const float* __restrict__ aD,
                           const int* __restrict__ rowptr, const int* __restrict__ colsrc,
                           const float* __restrict__ b1,
                           __nv_bfloat16* __restrict__ x1h, __nv_bfloat16* __restrict__ x1l)
{
    int dst = blockIdx.x;
    int w = threadIdx.x >> 5, lane = threadIdx.x & 31;
    int beg = rowptr[dst], end = rowptr[dst + 1];
    float adv = aD[dst * NHEADS + w];

    float m = -3.4e38f;
    for (int e = beg; e < end; e++) {
        float v = aS[colsrc[e] * NHEADS + w] + adv;
        v = v > 0.f ? v : 0.2f * v;
        m = fmaxf(m, v);
    }
    float acc[8] = {0.f, 0.f, 0.f, 0.f, 0.f, 0.f, 0.f, 0.f};
    float sump = 0.f;
    for (int e = beg; e < end; e++) {
        int s = colsrc[e];
        float v = aS[s * NHEADS + w] + adv;
        v = v > 0.f ? v : 0.2f * v;
        float p = expf(v - m);
        sump += p;
        const float* hp = h1 + (size_t)s * F1 + w * Hd + lane;
#pragma unroll
        for (int u = 0; u < 8; u++) acc[u] += p * hp[u * 32];
    }
    float inv = 1.f / (sump + 1e-16f);
    size_t base = (size_t)dst * F1 + w * Hd + lane;
    const float* bp = b1 + w * Hd + lane;
#pragma unroll
    for (int u = 0; u < 8; u++) {
        float o = acc[u] * inv + bp[u * 32];
        o = o > 0.f ? o : expm1f(o);           // ELU
        __nv_bfloat16 h, l; split_bf16(o, h, l);
        x1h[base + u * 32] = h;
        x1l[base + u * 32] = l;
    }
}

__global__ void k_gat2_agg(const float* __restrict__ h2,
                           const float* __restrict__ aS, const float* __restrict__ aD,
                           const int* __restrict__ rowptr, const int* __restrict__ colsrc,
                           const float* __restrict__ b2,
                           __nv_bfloat16* __restrict__ o2h, __nv_bfloat16* __restrict__ o2l)
{
    int dst = blockIdx.x, t = threadIdx.x;
    int beg = rowptr[dst], end = rowptr[dst + 1];
    float adv = aD[dst];
    float m = -3.4e38f;
    for (int e = beg; e < end; e++) {
        float v = aS[colsrc[e]] + adv;
        v = v > 0.f ? v : 0.2f * v;
        m = fmaxf(m, v);
    }
    float acc = 0.f, sump = 0.f;
    for (int e = beg; e < end; e++) {
        int s = colsrc[e];
        float v = aS[s] + adv;
        v = v > 0.f ? v : 0.2f * v;
        float p = expf(v - m);
        sump += p;
        acc += p * h2[(size_t)s * Hd + t];
    }
    float o = acc / (sump + 1e-16f) + b2[t];
    __nv_bfloat16 h, l; split_bf16(o, h, l);
    o2h[(size_t)dst * Hd + t] = h;
    o2l[(size_t)dst * Hd + t] = l;
}

// ---------------- sequence bookkeeping ----------------
// merged: zero len (256), bsum (1024), zero h (65536)  -> 65536 threads
__global__ void k_init_misc(int* __restrict__ len, const float* __restrict__ bih,
                            const float* __restrict__ bhh, float* __restrict__ bs,
                            float* __restrict__ h)
{
    int i = blockIdx.x * blockDim.x + threadIdx.x;
    if (i < Bsz) len[i] = 0;
    if (i < G4) bs[i] = bih[i] + bhh[i];
    h[i] = 0.f;   // i < Bsz*Hd == grid size
}
__global__ void k_count_len(const int* __restrict__ batch, int* __restrict__ len)
{
    int i = blockIdx.x * blockDim.x + threadIdx.x;
    if (i < Nn) atomicAdd(&len[batch[i]], 1);
}
__global__ void k_scan256(const int* __restrict__ len, int* __restrict__ starts)
{
    __shared__ int wsum[8];
    int tid = threadIdx.x;
    int orig = len[tid];
    int v = orig;
    int lane = tid & 31, wid = tid >> 5;
#pragma unroll
    for (int o = 1; o < 32; o <<= 1) {
        int t2 = __shfl_up_sync(0xffffffffu, v, o);
        if (lane >= o) v += t2;
    }
    if (lane == 31) wsum[wid] = v;
    __syncthreads();
    if (tid == 0) {
        int s = 0;
#pragma unroll
        for (int u = 0; u < 8; u++) { int t2 = wsum[u]; wsum[u] = s; s += t2; }
    }
    __syncthreads();
    starts[tid] = (v - orig) + wsum[wid];
}
__global__ void k_nodeidx(const int* __restrict__ batch, const int* __restrict__ starts,
                          int* __restrict__ nodeidx)
{
    int i = blockIdx.x * blockDim.x + threadIdx.x;
    if (i < Nn) {
        int b = batch[i];
        int p = i - starts[b];
        if (p >= 0 && p < Lseq) nodeidx[b * Lseq + p] = i;
    }
}

// ---------------- persistent fused LSTM ----------------
#define WST 68
__global__ void __launch_bounds__(256, 1)
k_lstm(const float* __restrict__ xg, const int* __restrict__ nodeidx,
       const int* __restrict__ len, float* __restrict__ hbuf0,
       float* __restrict__ hbuf1, const float* __restrict__ Whh)
{
    extern __shared__ float sm[];
    float* WshT = sm;
    float* HshT = sm + 256 * WST;
    float* red  = HshT + 256 * 33;
    float* csh  = red + 4 * 64 * 33;

    const int tid  = threadIdx.x;
    const int jb   = blockIdx.x & 15;
    const int mb   = blockIdx.x >> 4;
    const int kg   = tid >> 6;
    const int t64  = tid & 63;
    const int rowq = t64 & 15;
    const int bq   = t64 >> 4;

    unsigned my_gen = atomicAdd(&g_bar_gen, 0u);

    for (int idx = tid; idx < 64 * 256; idx += 256) {
        int r = idx >> 8;
        int k = idx & 255;
        int g = r >> 4, u = r & 15;
        WshT[k * WST + r] = Whh[(size_t)(g * 256 + jb * 16 + u) * 256 + k];
    }
    if (tid < 256) { csh[tid & 511] = 0.f; if (tid + 256 < 512) csh[tid + 256] = 0.f; }

    for (int t = 0; t < Lseq; t++) {
        const float* hc = (t & 1) ? hbuf1 : hbuf0;
#pragma unroll
        for (int l = 0; l < 32; l++) {
            int idx = tid + l * 256;
            int bl = idx >> 8, k = idx & 255;
            HshT[k * 33 + bl] = __ldcg(&hc[(mb * 32 + bl) * 256 + k]);
        }
        __syncthreads();

        float acc[4][8];
#pragma unroll
        for (int i = 0; i < 4; i++)
#pragma unroll
            for (int j = 0; j < 8; j++) acc[i][j] = 0.f;
        const int k0 = kg * 64;
#pragma unroll 4
        for (int k = k0; k < k0 + 64; k++) {
            float4 w = *reinterpret_cast<const float4*>(&WshT[k * WST + rowq * 4]);
            const float* hr = &HshT[k * 33 + bq * 8];
#pragma unroll
            for (int j = 0; j < 8; j++) {
                float hv = hr[j];
                acc[0][j] += w.x * hv;
                acc[1][j] += w.y * hv;
                acc[2][j] += w.z * hv;
                acc[3][j] += w.w * hv;
            }
        }
#pragma unroll
        for (int i = 0; i < 4; i++)
#pragma unroll
            for (int j = 0; j < 8; j++)
                red[kg * (64 * 33) + (rowq * 4 + i) * 33 + bq * 8 + j] = acc[i][j];
        __syncthreads();

        float* hn_buf = (t & 1) ? hbuf0 : hbuf1;
#pragma unroll
        for (int p = tid; p < 512; p += 256) {
            int u = p & 15;
            int bl = p >> 4;
            int bglob = mb * 32 + bl;
            int node = nodeidx[bglob * Lseq + t];
            const float* xp = xg + (size_t)node * G4 + jb * 16 + u;
            float gi = 0.f, gf = 0.f, gg = 0.f, go = 0.f;
#pragma unroll
            for (int q = 0; q < 4; q++) {
                const float* rq = red + q * (64 * 33);
                gi += rq[(0 * 16 + u) * 33 + bl];
                gf += rq[(1 * 16 + u) * 33 + bl];
                gg += rq[(2 * 16 + u) * 33 + bl];
                go += rq[(3 * 16 + u) * 33 + bl];
            }
            gi += xp[0]; gf += xp[256]; gg += xp[512]; go += xp[768];
            float hprev = HshT[(jb * 16 + u) * 33 + bl];
            float cprev = csh[u * 32 + bl];
            float si = 1.f / (1.f + expf(-gi));
            float sf = 1.f / (1.f + expf(-gf));
            float so = 1.f / (1.f + expf(-go));
            float cn = sf * cprev + si * tanhf(gg);
            float hn = so * tanhf(cn);
            bool act = (t < len[bglob]);
            if (act) csh[u * 32 + bl] = cn;
            float hw = act ? hn : hprev;
            __stcg(&hn_buf[bglob * 256 + jb * 16 + u], hw);
        }

        if (t != Lseq - 1) {
            __threadfence();
            __syncthreads();
            if (tid == 0) {
                unsigned old = atomicAdd(&g_bar_arrive, 1u);
                if (old == LSTM_BLOCKS - 1) {
                    atomicExch(&g_bar_arrive, 0u);
                    __threadfence();
                    atomicAdd(&g_bar_gen, 1u);
                } else {
                    while (atomicAdd(&g_bar_gen, 0u) == my_gen) __nanosleep(64);
                }
            }
            __syncthreads();
            my_gen++;
        }
    }
}

// ---------------- host launcher ----------------
extern "C" void kernel_launch(void* const* d_in, const int* in_sizes, int n_in,
                              void* d_out, int out_size)
{
    const int*   x_ids = (const int*)d_in[0];
    const int*   ei    = (const int*)d_in[1];
    const int*   batch = (const int*)d_in[2];
    const float* emb   = (const float*)d_in[3];
    const float* W1    = (const float*)d_in[4];
    const float* attS1 = (const float*)d_in[5];
    const float* attD1 = (const float*)d_in[6];
    const float* b1    = (const float*)d_in[7];
    const float* W2    = (const float*)d_in[8];
    const float* attS2 = (const float*)d_in[9];
    const float* attD2 = (const float*)d_in[10];
    const float* b2    = (const float*)d_in[11];
    const float* Wih   = (const float*)d_in[12];
    const float* Whh   = (const float*)d_in[13];
    const float* bih   = (const float*)d_in[14];
    const float* bhh   = (const float*)d_in[15];
    const float* Wp    = (const float*)d_in[16];
    const float* bp    = (const float*)d_in[17];
    float* out = (float*)d_out;

    void* p;
    cudaGetSymbolAddress(&p, g_h1);      float* h1   = (float*)p;
    cudaGetSymbolAddress(&p, g_h2);      float* h2   = (float*)p;
    cudaGetSymbolAddress(&p, g_xg);      float* xg   = (float*)p;
    cudaGetSymbolAddress(&p, g_as1);     float* as1  = (float*)p;
    cudaGetSymbolAddress(&p, g_ad1);     float* ad1  = (float*)p;
    cudaGetSymbolAddress(&p, g_as2);     float* as2  = (float*)p;
    cudaGetSymbolAddress(&p, g_ad2);     float* ad2  = (float*)p;
    cudaGetSymbolAddress(&p, g_counts);  int* counts = (int*)p;
    cudaGetSymbolAddress(&p, g_rowptr);  int* rowptr = (int*)p;
    cudaGetSymbolAddress(&p, g_cursor);  int* cursor = (int*)p;
    cudaGetSymbolAddress(&p, g_colsrc);  int* colsrc = (int*)p;
    cudaGetSymbolAddress(&p, g_len);     int* len    = (int*)p;
    cudaGetSymbolAddress(&p, g_starts);  int* starts = (int*)p;
    cudaGetSymbolAddress(&p, g_nodeidx); int* nodeidx= (int*)p;
    cudaGetSymbolAddress(&p, g_hbuf1);   float* hb1  = (float*)p;
    cudaGetSymbolAddress(&p, g_h);       float* hS   = (float*)p;
    cudaGetSymbolAddress(&p, g_bsum);    float* bsum = (float*)p;

    __nv_bfloat16 *x0h, *x0l, *x1h, *x1l, *o2h, *o2l;
    __nv_bfloat16 *W1Th, *W1Tl, *W2Th, *W2Tl, *Wihh, *Wihl, *hTh, *hTl, *Wph, *Wpl;
    cudaGetSymbolAddress(&p, g_x0h); x0h = (__nv_bfloat16*)p;
    cudaGetSymbolAddress(&p, g_x0l); x0l = (__nv_bfloat16*)p;
    cudaGetSymbolAddress(&p, g_x1h); x1h = (__nv_bfloat16*)p;
    cudaGetSymbolAddress(&p, g_x1l); x1l = (__nv_bfloat16*)p;
    cudaGetSymbolAddress(&p, g_o2h); o2h = (__nv_bfloat16*)p;
    cudaGetSymbolAddress(&p, g_o2l); o2l = (__nv_bfloat16*)p;
    cudaGetSymbolAddress(&p, g_W1Th); W1Th = (__nv_bfloat16*)p;
    cudaGetSymbolAddress(&p, g_W1Tl); W1Tl = (__nv_bfloat16*)p;
    cudaGetSymbolAddress(&p, g_W2Th); W2Th = (__nv_bfloat16*)p;
    cudaGetSymbolAddress(&p, g_W2Tl); W2Tl = (__nv_bfloat16*)p;
    cudaGetSymbolAddress(&p, g_Wihh); Wihh = (__nv_bfloat16*)p;
    cudaGetSymbolAddress(&p, g_Wihl); Wihl = (__nv_bfloat16*)p;
    cudaGetSymbolAddress(&p, g_hTh);  hTh  = (__nv_bfloat16*)p;
    cudaGetSymbolAddress(&p, g_hTl);  hTl  = (__nv_bfloat16*)p;
    cudaGetSymbolAddress(&p, g_Wph);  Wph  = (__nv_bfloat16*)p;
    cudaGetSymbolAddress(&p, g_Wpl);  Wpl  = (__nv_bfloat16*)p;

    static const int LSTM_SMEM = (256 * WST + 256 * 33 + 4 * 64 * 33 + 512) * 4;
    cudaFuncSetAttribute(k_lstm, cudaFuncAttributeMaxDynamicSharedMemorySize, LSTM_SMEM);
    cudaFuncSetAttribute(k_gemm_bf3, cudaFuncAttributeMaxDynamicSharedMemorySize, GEMM_SMEM);

    // 1) embedding gather with fused bf16 split
    k_gather_x0<<<Nn, Hd>>>(x_ids, emb, x0h, x0l);

    // weight conversions (constant work, small)
    k_splitT<<<dim3(F1 / 32, Hd / 32), dim3(32, 8)>>>(W1, W1Th, W1Tl, Hd, F1);
    k_splitT<<<dim3(Hd / 32, F1 / 32), dim3(32, 8)>>>(W2, W2Th, W2Tl, F1, Hd);
    k_split<<<(G4 * Hd + 255) / 256, 256>>>(Wih, Wihh, Wihl, G4 * Hd);
    k_split<<<(NNODE_ * Hd + 255) / 256, 256>>>(Wp, Wph, Wpl, NNODE_ * Hd);

    // 2) h1 = x0 @ W1  (tensor cores, bf16x3, 2 CTAs/SM)
    k_gemm_bf3<<<dim3(F1 / GBN, Nn / GBM), 256, GEMM_SMEM>>>(
        x0h, x0l, W1Th, W1Tl, h1, Nn, F1, Hd, nullptr);

    // 3) attention logits (layer 1)
    k_alpha1<<<Nn, 256>>>(h1, attS1, attD1, as1, ad1);

    // 4) CSR by dst
    k_init_counts<<<Nn / 256, 256>>>(counts);
    k_count_edges<<<Ee / 256, 256>>>(ei, counts);
    k_scan16k<<<1, 1024>>>(counts, rowptr, cursor);
    k_scatter_edges<<<Ee / 256, 256>>>(ei, cursor, colsrc);
    k_scatter_loops<<<Nn / 256, 256>>>(cursor, colsrc);

    // 5) GAT1 aggregate + b1 + ELU -> x1 (bf16 split fused)
    k_gat1_agg<<<Nn, 256>>>(h1, as1, ad1, rowptr, colsrc, b1, x1h, x1l);

    // 6) h2 = x1 @ W2
    k_gemm_bf3<<<dim3(Hd / GBN, Nn / GBM), 256, GEMM_SMEM>>>(
        x1h, x1l, W2Th, W2Tl, h2, Nn, Hd, F1, nullptr);

    // 7) layer-2 logits
    k_alpha2<<<Nn, 256>>>(h2, attS2, attD2, as2, ad2);

    // 8) GAT2 aggregate + b2 -> out2 (bf16 split fused)
    k_gat2_agg<<<Nn, 256>>>(h2, as2, ad2, rowptr, colsrc, b2, o2h, o2l);

    // 9) sequence bookkeeping (merged init)
    k_init_misc<<<(Bsz * Hd) / 256, 256>>>(len, bih, bhh, bsum, hS);
    k_count_len<<<Nn / 256, 256>>>(batch, len);
    k_scan256<<<1, Bsz>>>(len, starts);
    k_nodeidx<<<Nn / 256, 256>>>(batch, starts, nodeidx);

    // 10) xg = out2 @ Wih^T + (bih + bhh)
    k_gemm_bf3<<<dim3(G4 / GBN, Nn / GBM), 256, GEMM_SMEM>>>(
        o2h, o2l, Wihh, Wihl, xg, Nn, G4, Hd, bsum);

    // 11) persistent fused LSTM
    k_lstm<<<LSTM_BLOCKS, 256, LSTM_SMEM>>>(xg, nodeidx, len, hS, hb1, Whh);

    // 12) out = hT @ Wp^T + bp
    k_split<<<(Bsz * Hd + 255) / 256, 256>>>(hS, hTh, hTl, Bsz * Hd);
    k_gemm_bf3<<<dim3((NNODE_ + GBN - 1) / GBN, Bsz / GBM), 256, GEMM_SMEM>>>(
        hTh, hTl, Wph, Wpl, out, Bsz, NNODE_, Hd, bp);
}